// round 10
// baseline (speedup 1.0000x reference)
#include <cuda_runtime.h>
#include <math.h>

#define BATCH 1024
#define WARPS_PER_BLOCK 8
#define BLOCK (WARPS_PER_BLOCK * 32)
#define MAX_STEPS 128

// Grid tabulation of g(t1, tau): NG points, tau_j = (j-1)*h, h = t1/NSEG
#define NG 12
#define NSEG 9
#define NBATCH 3

// Fast warp sum via integer redux (sm_80+). Fixed-point 2^-17 quantization via
// the float magic-number trick. Requires |sum| < 32 (tanh-bounded dot terms).
__device__ __forceinline__ float warp_sum(float v) {
    float biased = fmaf(v, 131072.0f, 12582912.0f);   // v*2^17 + 1.5*2^23
    int xi = __float_as_int(biased) - 0x4B400000;     // round(v*2^17)
    int s;
    asm("redux.sync.add.s32 %0, %1, 0xffffffff;" : "=r"(s) : "r"(xi));
    float fs = __int_as_float(s + 0x4B400000) - 12582912.0f;  // (float)s
    return fs * 7.62939453125e-06f;                   // * 2^-17
}

// Hardware MUFU tanh (sm_75+): ~16 cyc, max abs err ~5e-4
__device__ __forceinline__ float fast_tanh(float x) {
    float r;
    asm("tanh.approx.f32 %0, %1;" : "=f"(r) : "f"(x));
    return r;
}

// ---- Packed fp32x2 (Blackwell): exact fp32, half the issue slots ----
__device__ __forceinline__ unsigned long long pack_f32x2(float lo, float hi) {
    unsigned long long r;
    asm("mov.b64 %0, {%1, %2};" : "=l"(r) : "f"(lo), "f"(hi));
    return r;
}
__device__ __forceinline__ float2 unpack_f32x2(unsigned long long v) {
    float lo, hi;
    asm("mov.b64 {%0, %1}, %2;" : "=f"(lo), "=f"(hi) : "l"(v));
    return make_float2(lo, hi);
}
__device__ __forceinline__ unsigned long long fma_f32x2(
    unsigned long long a, unsigned long long b, unsigned long long c) {
    unsigned long long d;
    asm("fma.rn.f32x2 %0, %1, %2, %3;" : "=l"(d) : "l"(a), "l"(b), "l"(c));
    return d;
}

// theta MLP layer2+3. Weights pre-packed in per-lane 64-bit regs w2p[16]
// (pairs of column `lane` of tW2). hv broadcast via smem; dot product runs as
// 16 packed f32x2 FMAs (was 32 scalar) -> chain issue cost halves.
__device__ __forceinline__ float theta_eval(float pre, float ys, float tbw,
                                            float tb2r, float tw3r,
                                            const unsigned long long* __restrict__ w2p,
                                            float* __restrict__ hvbuf,
                                            int lane) {
    float hv = fast_tanh(fmaf(tbw, ys, pre));
    hvbuf[lane] = hv;
    __syncwarp();
    const ulonglong2* h2p = (const ulonglong2*)hvbuf;  // 4 x (4 packed floats)
    unsigned long long a0 = pack_f32x2(tb2r, 0.0f);
    unsigned long long a1 = pack_f32x2(0.0f, 0.0f);
    unsigned long long a2 = a1, a3 = a1;
    #pragma unroll
    for (int q = 0; q < 4; ++q) {
        ulonglong2 hA = h2p[2 * q];       // hv[8q..8q+3]
        ulonglong2 hB = h2p[2 * q + 1];   // hv[8q+4..8q+7]
        a0 = fma_f32x2(w2p[4 * q + 0], hA.x, a0);
        a1 = fma_f32x2(w2p[4 * q + 1], hA.y, a1);
        a2 = fma_f32x2(w2p[4 * q + 2], hB.x, a2);
        a3 = fma_f32x2(w2p[4 * q + 3], hB.y, a3);
    }
    float2 u0 = unpack_f32x2(a0), u1 = unpack_f32x2(a1);
    float2 u2 = unpack_f32x2(a2), u3 = unpack_f32x2(a3);
    float s01 = (u0.x + u0.y) + (u1.x + u1.y);
    float s23 = (u2.x + u2.y) + (u3.x + u3.y);
    float h2 = fast_tanh(s01 + s23);
    return warp_sum(tw3r * h2);
}

// 4-point Lagrange cubic interpolation of g at tau.
__device__ __forceinline__ float g_interp(const float* __restrict__ sGw,
                                          float tau, float inv_h) {
    float s = fmaf(tau, inv_h, 1.0f);
    float fi = floorf(s);
    int i = (int)fi;
    i = i < 1 ? 1 : (i > NSEG ? NSEG : i);
    float u = s - (float)i;
    float p0 = sGw[i - 1], p1 = sGw[i], p2 = sGw[i + 1], p3 = sGw[i + 2];
    float um1 = u - 1.0f, um2 = u - 2.0f, up1 = u + 1.0f;
    float w0 = (-1.0f / 6.0f) * u * um1 * um2;
    float w1 = 0.5f * up1 * um1 * um2;
    float w2 = -0.5f * up1 * u * um2;
    float w3 = (1.0f / 6.0f) * up1 * u * um1;
    return fmaf(w0, p0, fmaf(w1, p1, fmaf(w2, p2, w3 * p3)));
}

// ---------------------------------------------------------------------------
// Single fused kernel.
// ---------------------------------------------------------------------------
__global__ void __launch_bounds__(BLOCK, 1)
neural_ode_kernel(const float* __restrict__ t,
                  const float* __restrict__ pW1, const float* __restrict__ pb1,
                  const float* __restrict__ pW2, const float* __restrict__ pb2,
                  const float* __restrict__ pW3, const float* __restrict__ pb3,
                  const float* __restrict__ dW, const float* __restrict__ db,
                  const float* __restrict__ tW1, const float* __restrict__ tb1,
                  const float* __restrict__ tW2, const float* __restrict__ tb2,
                  const float* __restrict__ tW3, const float* __restrict__ tb3,
                  float* __restrict__ out) {
    __shared__ float sW2T[64 * 65];   // pW2 transposed, padded (prologue only)
    __shared__ float sT2T[32 * 33];   // tW2 transposed staging
    __shared__ float sW1a[64], sW1b[64], sPb1[64], sPb2[64], sw[64];
    __shared__ float sFoldP[4][64];
    __shared__ float sCp[64];
    __shared__ float sT1a[32], sT1b[32], sTb1[32], sTb2[32], sTw3[32];
    __shared__ float sScal[3];        // c_fold, db0, tb3_0
    __shared__ float sG[WARPS_PER_BLOCK][NG];
    __shared__ __align__(16) float2 sPair[WARPS_PER_BLOCK][2][4][32];
    __shared__ __align__(16) float sHv[WARPS_PER_BLOCK][2][32];

    int tid = threadIdx.x;
    for (int idx = tid; idx < 4096; idx += BLOCK) {
        int j = idx >> 6, k = idx & 63;
        sW2T[k * 65 + j] = pW2[idx];
    }
    for (int idx = tid; idx < 1024; idx += BLOCK) {
        int j = idx >> 5, k = idx & 31;
        sT2T[k * 33 + j] = tW2[idx];
    }
    // Cooperative decoder fold: w_j = sum_i dW[i]*pW3[i][j]
    {
        int q = tid >> 6, j = tid & 63;
        float p = 0.0f;
        #pragma unroll
        for (int i = 0; i < 16; ++i)
            p = fmaf(dW[q * 16 + i], pW3[(q * 16 + i) * 64 + j], p);
        sFoldP[q][j] = p;
    }
    if (tid < 64) {
        sW1a[tid] = pW1[2 * tid];
        sW1b[tid] = pW1[2 * tid + 1];
        sPb1[tid] = pb1[tid];
        sPb2[tid] = pb2[tid];
        sCp[tid]  = dW[tid] * pb3[tid];
    }
    if (tid < 32) {
        sT1a[tid] = tW1[2 * tid];
        sT1b[tid] = tW1[2 * tid + 1];
        sTb1[tid] = tb1[tid];
        sTb2[tid] = tb2[tid];
        sTw3[tid] = tW3[tid];
    }
    __syncthreads();
    if (tid < 64)
        sw[tid] = (sFoldP[0][tid] + sFoldP[1][tid]) + (sFoldP[2][tid] + sFoldP[3][tid]);
    if (tid == 0) {
        float c = 0.0f;
        #pragma unroll
        for (int i = 0; i < 64; ++i) c += sCp[i];
        sScal[0] = c;
        sScal[1] = db[0];
        sScal[2] = tb3[0];
    }
    __syncthreads();

    int warp = tid >> 5, lane = tid & 31;
    int b = blockIdx.x * WARPS_PER_BLOCK + warp;

    // theta layer-2 weight column -> packed 64-bit register pairs
    unsigned long long w2p[16];
    #pragma unroll
    for (int kk = 0; kk < 16; ++kk)
        w2p[kk] = pack_f32x2(sT2T[(2 * kk) * 33 + lane],
                             sT2T[(2 * kk + 1) * 33 + lane]);

    float w1a_lo = sW1a[lane],       w1b_lo = sW1b[lane];
    float w1a_hi = sW1a[lane + 32],  w1b_hi = sW1b[lane + 32];
    float b1_lo  = sPb1[lane],       b1_hi  = sPb1[lane + 32];
    float b2_lo  = sPb2[lane],       b2_hi  = sPb2[lane + 32];
    float w_lo   = sw[lane],         w_hi   = sw[lane + 32];
    float cfold = sScal[0], db0 = sScal[1], tb30 = sScal[2];

    float t1 = t[b];
    float h = t1 * (1.0f / (float)NSEG);

    // ---- Per-warp g-grid tabulation: NBATCH batches of 4 points.
    for (int batch = 0; batch < NBATCH; ++batch) {
        int j4 = batch * 4;
        int pb = batch & 1;
        float taus[4];
        #pragma unroll
        for (int s = 0; s < 4; ++s) taus[s] = (float)(j4 + s - 1) * h;

        #pragma unroll
        for (int s = 0; s < 4; ++s) {
            float lo = fast_tanh(fmaf(w1a_lo, t1, fmaf(w1b_lo, taus[s], b1_lo)));
            float hi = fast_tanh(fmaf(w1a_hi, t1, fmaf(w1b_hi, taus[s], b1_hi)));
            sPair[warp][pb][s][lane] = make_float2(lo, hi);
        }
        __syncwarp();

        float acc_lo[4], acc_hi[4];
        #pragma unroll
        for (int s = 0; s < 4; ++s) { acc_lo[s] = b2_lo; acc_hi[s] = b2_hi; }

        #pragma unroll 4
        for (int k = 0; k < 32; ++k) {
            float2 p0 = sPair[warp][pb][0][k];
            float2 p1 = sPair[warp][pb][1][k];
            float2 p2 = sPair[warp][pb][2][k];
            float2 p3 = sPair[warp][pb][3][k];
            float wA = sW2T[k * 65 + lane];
            float wB = sW2T[(k + 32) * 65 + lane];
            float wC = sW2T[k * 65 + lane + 32];
            float wD = sW2T[(k + 32) * 65 + lane + 32];
            acc_lo[0] = fmaf(wA, p0.x, fmaf(wB, p0.y, acc_lo[0]));
            acc_hi[0] = fmaf(wC, p0.x, fmaf(wD, p0.y, acc_hi[0]));
            acc_lo[1] = fmaf(wA, p1.x, fmaf(wB, p1.y, acc_lo[1]));
            acc_hi[1] = fmaf(wC, p1.x, fmaf(wD, p1.y, acc_hi[1]));
            acc_lo[2] = fmaf(wA, p2.x, fmaf(wB, p2.y, acc_lo[2]));
            acc_hi[2] = fmaf(wC, p2.x, fmaf(wD, p2.y, acc_hi[2]));
            acc_lo[3] = fmaf(wA, p3.x, fmaf(wB, p3.y, acc_lo[3]));
            acc_hi[3] = fmaf(wC, p3.x, fmaf(wD, p3.y, acc_hi[3]));
        }
        #pragma unroll
        for (int s = 0; s < 4; ++s) {
            float v = fmaf(w_lo, fast_tanh(acc_lo[s]), w_hi * fast_tanh(acc_hi[s]));
            v = warp_sum(v) + cfold;
            if (lane == 0) sG[warp][j4 + s] = v;
        }
        __syncwarp();
    }
    const float* sGw = sG[warp];

    float ta  = sT1a[lane], tbw = sT1b[lane], tb1r = sTb1[lane];
    float tb2r = sTb2[lane], tw3r = sTw3[lane];

    const float C2 = 0.2f, C3 = 0.3f, C4 = 0.8f, C5 = (float)(8.0 / 9.0);
    const float A21 = 0.2f;
    const float A31 = (float)(3.0 / 40.0),   A32 = (float)(9.0 / 40.0);
    const float A41 = (float)(44.0 / 45.0),  A42 = (float)(-56.0 / 15.0), A43 = (float)(32.0 / 9.0);
    const float A51 = (float)(19372.0 / 6561.0), A52 = (float)(-25360.0 / 2187.0);
    const float A53 = (float)(64448.0 / 6561.0), A54 = (float)(-212.0 / 729.0);
    const float A61 = (float)(9017.0 / 3168.0),  A62 = (float)(-355.0 / 33.0);
    const float A63 = (float)(46732.0 / 5247.0), A64 = (float)(49.0 / 176.0);
    const float A65 = (float)(-5103.0 / 18656.0);
    const float B1 = (float)(35.0 / 384.0), B3 = (float)(500.0 / 1113.0);
    const float B4 = (float)(125.0 / 192.0), B5 = (float)(-2187.0 / 6784.0);
    const float B6 = (float)(11.0 / 84.0);
    const float E1 = (float)(35.0 / 384.0 - 5179.0 / 57600.0);
    const float E3 = (float)(500.0 / 1113.0 - 7571.0 / 16695.0);
    const float E4 = (float)(125.0 / 192.0 - 393.0 / 640.0);
    const float E5 = (float)(-2187.0 / 6784.0 + 92097.0 / 339200.0);
    const float E6 = (float)(11.0 / 84.0 - 187.0 / 2100.0);
    const float E7 = (float)(-1.0 / 40.0);
    const float RTOL = 1e-3f, ATOL = 1e-6f;
    const float SAFETY = 0.9f, FMIN = 0.2f, FMAX = 10.0f;

    float inv_h = __fdividef((float)NSEG, t1);
    float tau = 0.0f, y = 0.0f, dt = 0.01f;

    int tb = 0;  // double-buffer parity for hv broadcasts

    // FSAL: f1 = theta(tau, y); updated via the f7 hand-off on accept.
    float f1 = theta_eval(tb1r, 0.0f, tbw, tb2r, tw3r, w2p, sHv[warp][tb], lane) + tb30;

    for (int it = 0; it < MAX_STEPS; ++it) {
        float remaining = t1 - tau;
        if (remaining <= 1e-10f) break;
        float dt_eff = fminf(dt, remaining);

        float taus[6];
        taus[0] = tau;
        taus[1] = tau + C2 * dt_eff;
        taus[2] = tau + C3 * dt_eff;
        taus[3] = tau + C4 * dt_eff;
        taus[4] = tau + C5 * dt_eff;
        taus[5] = tau + dt_eff;

        float g[6];
        #pragma unroll
        for (int s = 0; s < 6; ++s) g[s] = g_interp(sGw, taus[s], inv_h);

        float pre[6];
        #pragma unroll
        for (int s = 0; s < 6; ++s) pre[s] = fmaf(ta, taus[s], tb1r);

        float k1 = fmaf(g[0], f1, db0);

        float y2 = fmaf(dt_eff, A21 * k1, y);
        tb ^= 1;
        float f2 = theta_eval(pre[1], y2, tbw, tb2r, tw3r, w2p, sHv[warp][tb], lane) + tb30;
        float k2 = fmaf(g[1], f2, db0);

        float y3 = fmaf(dt_eff, fmaf(A31, k1, A32 * k2), y);
        tb ^= 1;
        float f3 = theta_eval(pre[2], y3, tbw, tb2r, tw3r, w2p, sHv[warp][tb], lane) + tb30;
        float k3 = fmaf(g[2], f3, db0);

        float y4 = fmaf(dt_eff, fmaf(A41, k1, fmaf(A42, k2, A43 * k3)), y);
        tb ^= 1;
        float f4 = theta_eval(pre[3], y4, tbw, tb2r, tw3r, w2p, sHv[warp][tb], lane) + tb30;
        float k4 = fmaf(g[3], f4, db0);

        float y5i = fmaf(dt_eff, fmaf(A51, k1, fmaf(A52, k2, fmaf(A53, k3, A54 * k4))), y);
        tb ^= 1;
        float f5 = theta_eval(pre[4], y5i, tbw, tb2r, tw3r, w2p, sHv[warp][tb], lane) + tb30;
        float k5 = fmaf(g[4], f5, db0);

        float y6 = fmaf(dt_eff, fmaf(A61, k1, fmaf(A62, k2, fmaf(A63, k3, fmaf(A64, k4, A65 * k5)))), y);
        tb ^= 1;
        float f6 = theta_eval(pre[5], y6, tbw, tb2r, tw3r, w2p, sHv[warp][tb], lane) + tb30;
        float k6 = fmaf(g[5], f6, db0);

        float y5 = fmaf(dt_eff,
                        fmaf(B1, k1, fmaf(B3, k3, fmaf(B4, k4, fmaf(B5, k5, B6 * k6)))),
                        y);
        tb ^= 1;
        float f7 = theta_eval(pre[5], y5, tbw, tb2r, tw3r, w2p, sHv[warp][tb], lane) + tb30;
        float k7 = fmaf(g[5], f7, db0);

        float err = dt_eff *
            fmaf(E1, k1, fmaf(E3, k3, fmaf(E4, k4, fmaf(E5, k5, fmaf(E6, k6, E7 * k7)))));
        float scale = fmaf(RTOL, fmaxf(fabsf(y), fabsf(y5)), ATOL);
        // sqrt-free controller: err_norm^2 = r2 (+eps); accept <=> r2 <= 1;
        // factor = SAFETY * (max(r2+1e-30,1e-20))^-0.1  (== en^-0.2)
        float r2 = __fdividef(err * err, scale * scale);
        bool accept = (r2 <= 1.0f);
        float en2 = fmaxf(r2 + 1e-30f, 1e-20f);
        float factor = SAFETY * exp2f(-0.1f * __log2f(en2));
        factor = fminf(fmaxf(factor, FMIN), FMAX);

        if (accept) {
            tau = tau + dt_eff;
            y = y5;
            f1 = f7;   // FSAL hand-off
        }
        dt = fmaxf(dt_eff * factor, 1e-8f);
    }

    if (lane == 0) out[b] = y;
}

extern "C" void kernel_launch(void* const* d_in, const int* in_sizes, int n_in,
                              void* d_out, int out_size) {
    const float* t    = (const float*)d_in[0];
    const float* pW1  = (const float*)d_in[1];
    const float* pb1  = (const float*)d_in[2];
    const float* pW2  = (const float*)d_in[3];
    const float* pb2  = (const float*)d_in[4];
    const float* pW3  = (const float*)d_in[5];
    const float* pb3  = (const float*)d_in[6];
    const float* dW   = (const float*)d_in[7];
    const float* db   = (const float*)d_in[8];
    const float* tW1  = (const float*)d_in[9];
    const float* tb1  = (const float*)d_in[10];
    const float* tW2  = (const float*)d_in[11];
    const float* tb2  = (const float*)d_in[12];
    const float* tW3  = (const float*)d_in[13];
    const float* tb3  = (const float*)d_in[14];
    float* out = (float*)d_out;

    neural_ode_kernel<<<BATCH / WARPS_PER_BLOCK, BLOCK>>>(
        t, pW1, pb1, pW2, pb2, pW3, pb3, dW, db,
        tW1, tb1, tW2, tb2, tW3, tb3, out);
}

// round 11
// speedup vs baseline: 1.0047x; 1.0047x over previous
#include <cuda_runtime.h>
#include <math.h>

#define BATCH 1024
#define WARPS_PER_BLOCK 8
#define BLOCK (WARPS_PER_BLOCK * 32)
#define MAX_STEPS 128

// Grid tabulation of g(t1, tau): NG points, tau_j = (j-1)*h, h = t1/NSEG
#define NG 12
#define NSEG 9
#define NBATCH 3

#define INV17 7.62939453125e-06f   // 2^-17

// Fast warp sum via integer redux (sm_80+). Fixed-point 2^-17 quantization.
__device__ __forceinline__ float warp_sum(float v) {
    float biased = fmaf(v, 131072.0f, 12582912.0f);   // v*2^17 + 1.5*2^23
    int xi = __float_as_int(biased) - 0x4B400000;     // round(v*2^17)
    int s;
    asm("redux.sync.add.s32 %0, %1, 0xffffffff;" : "=r"(s) : "r"(xi));
    float fs = __int_as_float(s + 0x4B400000) - 12582912.0f;  // (float)s
    return fs * INV17;
}

// Hardware MUFU tanh (sm_75+): ~16 cyc, max abs err ~5e-4
__device__ __forceinline__ float fast_tanh(float x) {
    float r;
    asm("tanh.approx.f32 %0, %1;" : "=f"(r) : "f"(x));
    return r;
}

// ---- Packed fp32x2 (Blackwell): exact fp32, half the issue slots ----
__device__ __forceinline__ unsigned long long pack_f32x2(float lo, float hi) {
    unsigned long long r;
    asm("mov.b64 %0, {%1, %2};" : "=l"(r) : "f"(lo), "f"(hi));
    return r;
}
__device__ __forceinline__ float2 unpack_f32x2(unsigned long long v) {
    float lo, hi;
    asm("mov.b64 {%0, %1}, %2;" : "=f"(lo), "=f"(hi) : "l"(v));
    return make_float2(lo, hi);
}
__device__ __forceinline__ unsigned long long fma_f32x2(
    unsigned long long a, unsigned long long b, unsigned long long c) {
    unsigned long long d;
    asm("fma.rn.f32x2 %0, %1, %2, %3;" : "=l"(d) : "l"(a), "l"(b), "l"(c));
    return d;
}

// theta MLP layer2+3, RAW tail: returns fs = quantized-count of
// sum_lanes(tw3*h2) scaled by 2^17. Caller folds: f = fs*2^-17 + tb3;
// k = g*f + db  ==  fmaf(fs, g*2^-17, g*tb3 + db) with both coefficients
// precomputed OFF the serial chain.
// Convergent-warp STS->LDS broadcast without WARPSYNC: per-warp in-order
// issue + per-warp in-order MIO ordering; compiler barrier stops reordering.
__device__ __forceinline__ float theta_raw(float pre, float ys, float tbw,
                                           float tb2r, float tw3r,
                                           const unsigned long long* __restrict__ w2p,
                                           float* __restrict__ hvbuf,
                                           int lane) {
    float hv = fast_tanh(fmaf(tbw, ys, pre));
    hvbuf[lane] = hv;
    asm volatile("" ::: "memory");
    const ulonglong2* h2p = (const ulonglong2*)hvbuf;  // 4 x (4 packed floats)
    unsigned long long a0 = pack_f32x2(tb2r, 0.0f);
    unsigned long long a1 = pack_f32x2(0.0f, 0.0f);
    unsigned long long a2 = a1, a3 = a1;
    #pragma unroll
    for (int q = 0; q < 4; ++q) {
        ulonglong2 hA = h2p[2 * q];       // hv[8q..8q+3]
        ulonglong2 hB = h2p[2 * q + 1];   // hv[8q+4..8q+7]
        a0 = fma_f32x2(w2p[4 * q + 0], hA.x, a0);
        a1 = fma_f32x2(w2p[4 * q + 1], hA.y, a1);
        a2 = fma_f32x2(w2p[4 * q + 2], hB.x, a2);
        a3 = fma_f32x2(w2p[4 * q + 3], hB.y, a3);
    }
    float2 u0 = unpack_f32x2(a0), u1 = unpack_f32x2(a1);
    float2 u2 = unpack_f32x2(a2), u3 = unpack_f32x2(a3);
    float s01 = (u0.x + u0.y) + (u1.x + u1.y);
    float s23 = (u2.x + u2.y) + (u3.x + u3.y);
    float h2 = fast_tanh(s01 + s23);
    float v = tw3r * h2;
    float biased = fmaf(v, 131072.0f, 12582912.0f);
    int xi = __float_as_int(biased) - 0x4B400000;
    int s;
    asm("redux.sync.add.s32 %0, %1, 0xffffffff;" : "=r"(s) : "r"(xi));
    return __int_as_float(s + 0x4B400000) - 12582912.0f;   // (float)sum*2^17
}

// 4-point Lagrange cubic interpolation of g at tau.
__device__ __forceinline__ float g_interp(const float* __restrict__ sGw,
                                          float tau, float inv_h) {
    float s = fmaf(tau, inv_h, 1.0f);
    float fi = floorf(s);
    int i = (int)fi;
    i = i < 1 ? 1 : (i > NSEG ? NSEG : i);
    float u = s - (float)i;
    float p0 = sGw[i - 1], p1 = sGw[i], p2 = sGw[i + 1], p3 = sGw[i + 2];
    float um1 = u - 1.0f, um2 = u - 2.0f, up1 = u + 1.0f;
    float w0 = (-1.0f / 6.0f) * u * um1 * um2;
    float w1 = 0.5f * up1 * um1 * um2;
    float w2 = -0.5f * up1 * u * um2;
    float w3 = (1.0f / 6.0f) * up1 * u * um1;
    return fmaf(w0, p0, fmaf(w1, p1, fmaf(w2, p2, w3 * p3)));
}

// ---------------------------------------------------------------------------
// Single fused kernel.
// ---------------------------------------------------------------------------
__global__ void __launch_bounds__(BLOCK, 1)
neural_ode_kernel(const float* __restrict__ t,
                  const float* __restrict__ pW1, const float* __restrict__ pb1,
                  const float* __restrict__ pW2, const float* __restrict__ pb2,
                  const float* __restrict__ pW3, const float* __restrict__ pb3,
                  const float* __restrict__ dW, const float* __restrict__ db,
                  const float* __restrict__ tW1, const float* __restrict__ tb1,
                  const float* __restrict__ tW2, const float* __restrict__ tb2,
                  const float* __restrict__ tW3, const float* __restrict__ tb3,
                  float* __restrict__ out) {
    __shared__ float sW2T[64 * 65];   // pW2 transposed, padded (prologue only)
    __shared__ float sT2T[32 * 33];   // tW2 transposed staging
    __shared__ float sW1a[64], sW1b[64], sPb1[64], sPb2[64], sw[64];
    __shared__ float sFoldP[4][64];
    __shared__ float sCp[64];
    __shared__ float sT1a[32], sT1b[32], sTb1[32], sTb2[32], sTw3[32];
    __shared__ float sScal[3];        // c_fold, db0, tb3_0
    __shared__ float sG[WARPS_PER_BLOCK][NG];
    __shared__ __align__(16) float2 sPair[WARPS_PER_BLOCK][2][4][32];
    __shared__ __align__(16) float sHv[WARPS_PER_BLOCK][2][32];

    int tid = threadIdx.x;
    for (int idx = tid; idx < 4096; idx += BLOCK) {
        int j = idx >> 6, k = idx & 63;
        sW2T[k * 65 + j] = pW2[idx];
    }
    for (int idx = tid; idx < 1024; idx += BLOCK) {
        int j = idx >> 5, k = idx & 31;
        sT2T[k * 33 + j] = tW2[idx];
    }
    // Cooperative decoder fold: w_j = sum_i dW[i]*pW3[i][j]
    {
        int q = tid >> 6, j = tid & 63;
        float p = 0.0f;
        #pragma unroll
        for (int i = 0; i < 16; ++i)
            p = fmaf(dW[q * 16 + i], pW3[(q * 16 + i) * 64 + j], p);
        sFoldP[q][j] = p;
    }
    if (tid < 64) {
        sW1a[tid] = pW1[2 * tid];
        sW1b[tid] = pW1[2 * tid + 1];
        sPb1[tid] = pb1[tid];
        sPb2[tid] = pb2[tid];
        sCp[tid]  = dW[tid] * pb3[tid];
    }
    if (tid < 32) {
        sT1a[tid] = tW1[2 * tid];
        sT1b[tid] = tW1[2 * tid + 1];
        sTb1[tid] = tb1[tid];
        sTb2[tid] = tb2[tid];
        sTw3[tid] = tW3[tid];
    }
    __syncthreads();
    if (tid < 64)
        sw[tid] = (sFoldP[0][tid] + sFoldP[1][tid]) + (sFoldP[2][tid] + sFoldP[3][tid]);
    if (tid == 0) {
        float c = 0.0f;
        #pragma unroll
        for (int i = 0; i < 64; ++i) c += sCp[i];
        sScal[0] = c;
        sScal[1] = db[0];
        sScal[2] = tb3[0];
    }
    __syncthreads();

    int warp = tid >> 5, lane = tid & 31;
    int b = blockIdx.x * WARPS_PER_BLOCK + warp;

    // theta layer-2 weight column -> packed 64-bit register pairs
    unsigned long long w2p[16];
    #pragma unroll
    for (int kk = 0; kk < 16; ++kk)
        w2p[kk] = pack_f32x2(sT2T[(2 * kk) * 33 + lane],
                             sT2T[(2 * kk + 1) * 33 + lane]);

    float w1a_lo = sW1a[lane],       w1b_lo = sW1b[lane];
    float w1a_hi = sW1a[lane + 32],  w1b_hi = sW1b[lane + 32];
    float b1_lo  = sPb1[lane],       b1_hi  = sPb1[lane + 32];
    float b2_lo  = sPb2[lane],       b2_hi  = sPb2[lane + 32];
    float w_lo   = sw[lane],         w_hi   = sw[lane + 32];
    float cfold = sScal[0], db0 = sScal[1], tb30 = sScal[2];

    float t1 = t[b];
    float h = t1 * (1.0f / (float)NSEG);

    // ---- Per-warp g-grid tabulation: NBATCH batches of 4 points.
    for (int batch = 0; batch < NBATCH; ++batch) {
        int j4 = batch * 4;
        int pb = batch & 1;
        float taus[4];
        #pragma unroll
        for (int s = 0; s < 4; ++s) taus[s] = (float)(j4 + s - 1) * h;

        #pragma unroll
        for (int s = 0; s < 4; ++s) {
            float lo = fast_tanh(fmaf(w1a_lo, t1, fmaf(w1b_lo, taus[s], b1_lo)));
            float hi = fast_tanh(fmaf(w1a_hi, t1, fmaf(w1b_hi, taus[s], b1_hi)));
            sPair[warp][pb][s][lane] = make_float2(lo, hi);
        }
        __syncwarp();

        float acc_lo[4], acc_hi[4];
        #pragma unroll
        for (int s = 0; s < 4; ++s) { acc_lo[s] = b2_lo; acc_hi[s] = b2_hi; }

        #pragma unroll 4
        for (int k = 0; k < 32; ++k) {
            float2 p0 = sPair[warp][pb][0][k];
            float2 p1 = sPair[warp][pb][1][k];
            float2 p2 = sPair[warp][pb][2][k];
            float2 p3 = sPair[warp][pb][3][k];
            float wA = sW2T[k * 65 + lane];
            float wB = sW2T[(k + 32) * 65 + lane];
            float wC = sW2T[k * 65 + lane + 32];
            float wD = sW2T[(k + 32) * 65 + lane + 32];
            acc_lo[0] = fmaf(wA, p0.x, fmaf(wB, p0.y, acc_lo[0]));
            acc_hi[0] = fmaf(wC, p0.x, fmaf(wD, p0.y, acc_hi[0]));
            acc_lo[1] = fmaf(wA, p1.x, fmaf(wB, p1.y, acc_lo[1]));
            acc_hi[1] = fmaf(wC, p1.x, fmaf(wD, p1.y, acc_hi[1]));
            acc_lo[2] = fmaf(wA, p2.x, fmaf(wB, p2.y, acc_lo[2]));
            acc_hi[2] = fmaf(wC, p2.x, fmaf(wD, p2.y, acc_hi[2]));
            acc_lo[3] = fmaf(wA, p3.x, fmaf(wB, p3.y, acc_lo[3]));
            acc_hi[3] = fmaf(wC, p3.x, fmaf(wD, p3.y, acc_hi[3]));
        }
        #pragma unroll
        for (int s = 0; s < 4; ++s) {
            float v = fmaf(w_lo, fast_tanh(acc_lo[s]), w_hi * fast_tanh(acc_hi[s]));
            v = warp_sum(v) + cfold;
            if (lane == 0) sG[warp][j4 + s] = v;
        }
        __syncwarp();
    }
    const float* sGw = sG[warp];

    float ta  = sT1a[lane], tbw = sT1b[lane], tb1r = sTb1[lane];
    float tb2r = sTb2[lane], tw3r = sTw3[lane];

    const float C2 = 0.2f, C3 = 0.3f, C4 = 0.8f, C5 = (float)(8.0 / 9.0);
    const float A21 = 0.2f;
    const float A31 = (float)(3.0 / 40.0),   A32 = (float)(9.0 / 40.0);
    const float A41 = (float)(44.0 / 45.0),  A42 = (float)(-56.0 / 15.0), A43 = (float)(32.0 / 9.0);
    const float A51 = (float)(19372.0 / 6561.0), A52 = (float)(-25360.0 / 2187.0);
    const float A53 = (float)(64448.0 / 6561.0), A54 = (float)(-212.0 / 729.0);
    const float A61 = (float)(9017.0 / 3168.0),  A62 = (float)(-355.0 / 33.0);
    const float A63 = (float)(46732.0 / 5247.0), A64 = (float)(49.0 / 176.0);
    const float A65 = (float)(-5103.0 / 18656.0);
    const float B1 = (float)(35.0 / 384.0), B3 = (float)(500.0 / 1113.0);
    const float B4 = (float)(125.0 / 192.0), B5 = (float)(-2187.0 / 6784.0);
    const float B6 = (float)(11.0 / 84.0);
    const float E1 = (float)(35.0 / 384.0 - 5179.0 / 57600.0);
    const float E3 = (float)(500.0 / 1113.0 - 7571.0 / 16695.0);
    const float E4 = (float)(125.0 / 192.0 - 393.0 / 640.0);
    const float E5 = (float)(-2187.0 / 6784.0 + 92097.0 / 339200.0);
    const float E6 = (float)(11.0 / 84.0 - 187.0 / 2100.0);
    const float E7 = (float)(-1.0 / 40.0);
    const float RTOL = 1e-3f, ATOL = 1e-6f;
    const float SAFETY = 0.9f, FMIN = 0.2f, FMAX = 10.0f;

    float inv_h = __fdividef((float)NSEG, t1);
    float tau = 0.0f, y = 0.0f, dt = 0.01f;

    int tb = 0;  // buffer parity for hv broadcasts

    // FSAL carries: fs1 = raw theta count at (tau, y); g0 = g(tau).
    float fs1 = theta_raw(tb1r, 0.0f, tbw, tb2r, tw3r, w2p, sHv[warp][tb], lane);
    float g0  = g_interp(sGw, 0.0f, inv_h);

    for (int it = 0; it < MAX_STEPS; ++it) {
        float remaining = t1 - tau;
        if (remaining <= 1e-10f) break;
        float dt_eff = fminf(dt, remaining);

        float taus[6];
        taus[1] = tau + C2 * dt_eff;
        taus[2] = tau + C3 * dt_eff;
        taus[3] = tau + C4 * dt_eff;
        taus[4] = tau + C5 * dt_eff;
        taus[5] = tau + dt_eff;

        // g at stage taus (g[0] carried). Precompute per-stage affine folds:
        // k = fmaf(fs, gscl, gaff) with gscl = g*2^-17, gaff = g*tb3 + db.
        float g1 = g_interp(sGw, taus[1], inv_h);
        float g2 = g_interp(sGw, taus[2], inv_h);
        float g3 = g_interp(sGw, taus[3], inv_h);
        float g4 = g_interp(sGw, taus[4], inv_h);
        float g5 = g_interp(sGw, taus[5], inv_h);
        float g0scl = g0 * INV17, g0aff = fmaf(g0, tb30, db0);
        float g1scl = g1 * INV17, g1aff = fmaf(g1, tb30, db0);
        float g2scl = g2 * INV17, g2aff = fmaf(g2, tb30, db0);
        float g3scl = g3 * INV17, g3aff = fmaf(g3, tb30, db0);
        float g4scl = g4 * INV17, g4aff = fmaf(g4, tb30, db0);
        float g5scl = g5 * INV17, g5aff = fmaf(g5, tb30, db0);

        float pre1 = fmaf(ta, taus[1], tb1r);
        float pre2 = fmaf(ta, taus[2], tb1r);
        float pre3 = fmaf(ta, taus[3], tb1r);
        float pre4 = fmaf(ta, taus[4], tb1r);
        float pre5 = fmaf(ta, taus[5], tb1r);

        float k1 = fmaf(fs1, g0scl, g0aff);

        float y2 = fmaf(dt_eff, A21 * k1, y);
        tb ^= 1;
        float fs2 = theta_raw(pre1, y2, tbw, tb2r, tw3r, w2p, sHv[warp][tb], lane);
        float k2 = fmaf(fs2, g1scl, g1aff);

        float y3 = fmaf(dt_eff, fmaf(A31, k1, A32 * k2), y);
        tb ^= 1;
        float fs3 = theta_raw(pre2, y3, tbw, tb2r, tw3r, w2p, sHv[warp][tb], lane);
        float k3 = fmaf(fs3, g2scl, g2aff);

        float y4 = fmaf(dt_eff, fmaf(A41, k1, fmaf(A42, k2, A43 * k3)), y);
        tb ^= 1;
        float fs4 = theta_raw(pre3, y4, tbw, tb2r, tw3r, w2p, sHv[warp][tb], lane);
        float k4 = fmaf(fs4, g3scl, g3aff);

        float y5i = fmaf(dt_eff, fmaf(A51, k1, fmaf(A52, k2, fmaf(A53, k3, A54 * k4))), y);
        tb ^= 1;
        float fs5 = theta_raw(pre4, y5i, tbw, tb2r, tw3r, w2p, sHv[warp][tb], lane);
        float k5 = fmaf(fs5, g4scl, g4aff);

        float y6 = fmaf(dt_eff, fmaf(A61, k1, fmaf(A62, k2, fmaf(A63, k3, fmaf(A64, k4, A65 * k5)))), y);
        tb ^= 1;
        float fs6 = theta_raw(pre5, y6, tbw, tb2r, tw3r, w2p, sHv[warp][tb], lane);
        float k6 = fmaf(fs6, g5scl, g5aff);

        float y5 = fmaf(dt_eff,
                        fmaf(B1, k1, fmaf(B3, k3, fmaf(B4, k4, fmaf(B5, k5, B6 * k6)))),
                        y);
        tb ^= 1;
        float fs7 = theta_raw(pre5, y5, tbw, tb2r, tw3r, w2p, sHv[warp][tb], lane);
        float k7 = fmaf(fs7, g5scl, g5aff);

        float err = dt_eff *
            fmaf(E1, k1, fmaf(E3, k3, fmaf(E4, k4, fmaf(E5, k5, fmaf(E6, k6, E7 * k7)))));
        float scale = fmaf(RTOL, fmaxf(fabsf(y), fabsf(y5)), ATOL);
        // sqrt-free controller: accept <=> (err/scale)^2 <= 1;
        // factor = SAFETY * (r2)^-0.1 == SAFETY * en^-0.2
        float r2 = __fdividef(err * err, scale * scale);
        bool accept = (r2 <= 1.0f);
        float en2 = fmaxf(r2 + 1e-30f, 1e-20f);
        float factor = SAFETY * exp2f(-0.1f * __log2f(en2));
        factor = fminf(fmaxf(factor, FMIN), FMAX);

        if (accept) {
            tau = taus[5];   // == tau + dt_eff
            y = y5;
            fs1 = fs7;       // FSAL hand-off (raw count)
            g0 = g5;         // g(tau_new) == g[5] bitwise
        }
        dt = fmaxf(dt_eff * factor, 1e-8f);
    }

    if (lane == 0) out[b] = y;
}

extern "C" void kernel_launch(void* const* d_in, const int* in_sizes, int n_in,
                              void* d_out, int out_size) {
    const float* t    = (const float*)d_in[0];
    const float* pW1  = (const float*)d_in[1];
    const float* pb1  = (const float*)d_in[2];
    const float* pW2  = (const float*)d_in[3];
    const float* pb2  = (const float*)d_in[4];
    const float* pW3  = (const float*)d_in[5];
    const float* pb3  = (const float*)d_in[6];
    const float* dW   = (const float*)d_in[7];
    const float* db   = (const float*)d_in[8];
    const float* tW1  = (const float*)d_in[9];
    const float* tb1  = (const float*)d_in[10];
    const float* tW2  = (const float*)d_in[11];
    const float* tb2  = (const float*)d_in[12];
    const float* tW3  = (const float*)d_in[13];
    const float* tb3  = (const float*)d_in[14];
    float* out = (float*)d_out;

    neural_ode_kernel<<<BATCH / WARPS_PER_BLOCK, BLOCK>>>(
        t, pW1, pb1, pW2, pb2, pW3, pb3, dW, db,
        tW1, tb1, tW2, tb2, tW3, tb3, out);
}

// round 13
// speedup vs baseline: 1.0824x; 1.0773x over previous
#include <cuda_runtime.h>
#include <math.h>

#define BATCH 1024
#define WARPS_PER_BLOCK 8
#define BLOCK (WARPS_PER_BLOCK * 32)
#define MAX_STEPS 128

// Grid tabulation of g(t1, tau): NG points, tau_j = (j-1)*h, h = t1/NSEG
#define NG 8
#define NSEG 5
#define NBATCH 2

#define INV17 7.62939453125e-06f   // 2^-17

// Fast warp sum via integer redux (sm_80+). Fixed-point 2^-17 quantization.
__device__ __forceinline__ float warp_sum(float v) {
    float biased = fmaf(v, 131072.0f, 12582912.0f);   // v*2^17 + 1.5*2^23
    int xi = __float_as_int(biased) - 0x4B400000;     // round(v*2^17)
    int s;
    asm("redux.sync.add.s32 %0, %1, 0xffffffff;" : "=r"(s) : "r"(xi));
    float fs = __int_as_float(s + 0x4B400000) - 12582912.0f;  // (float)s
    return fs * INV17;
}

// Hardware MUFU tanh (sm_75+): ~16 cyc, max abs err ~5e-4
__device__ __forceinline__ float fast_tanh(float x) {
    float r;
    asm("tanh.approx.f32 %0, %1;" : "=f"(r) : "f"(x));
    return r;
}

// ---- Packed fp32x2 (Blackwell): exact fp32, half the issue slots ----
__device__ __forceinline__ unsigned long long pack_f32x2(float lo, float hi) {
    unsigned long long r;
    asm("mov.b64 %0, {%1, %2};" : "=l"(r) : "f"(lo), "f"(hi));
    return r;
}
__device__ __forceinline__ float2 unpack_f32x2(unsigned long long v) {
    float lo, hi;
    asm("mov.b64 {%0, %1}, %2;" : "=f"(lo), "=f"(hi) : "l"(v));
    return make_float2(lo, hi);
}
__device__ __forceinline__ unsigned long long fma_f32x2(
    unsigned long long a, unsigned long long b, unsigned long long c) {
    unsigned long long d;
    asm("fma.rn.f32x2 %0, %1, %2, %3;" : "=l"(d) : "l"(a), "l"(b), "l"(c));
    return d;
}

// theta MLP layer2+3, RAW tail: returns fs = quantized count of
// sum_lanes(tw3*h2) scaled 2^17. tw3q = tw3*2^17 folded into the quantizer
// (kills a serial FMUL). Caller folds: k = fmaf(fs, g*2^-17, g*tb3 + db).
__device__ __forceinline__ float theta_raw(float pre, float ys, float tbw,
                                           float tb2r, float tw3q,
                                           const unsigned long long* __restrict__ w2p,
                                           float* __restrict__ hvbuf,
                                           int lane) {
    float hv = fast_tanh(fmaf(tbw, ys, pre));
    hvbuf[lane] = hv;
    asm volatile("" ::: "memory");
    const ulonglong2* h2p = (const ulonglong2*)hvbuf;  // 4 x (4 packed floats)
    unsigned long long a0 = pack_f32x2(tb2r, 0.0f);
    unsigned long long a1 = pack_f32x2(0.0f, 0.0f);
    unsigned long long a2 = a1, a3 = a1;
    #pragma unroll
    for (int q = 0; q < 4; ++q) {
        ulonglong2 hA = h2p[2 * q];       // hv[8q..8q+3]
        ulonglong2 hB = h2p[2 * q + 1];   // hv[8q+4..8q+7]
        a0 = fma_f32x2(w2p[4 * q + 0], hA.x, a0);
        a1 = fma_f32x2(w2p[4 * q + 1], hA.y, a1);
        a2 = fma_f32x2(w2p[4 * q + 2], hB.x, a2);
        a3 = fma_f32x2(w2p[4 * q + 3], hB.y, a3);
    }
    float2 u0 = unpack_f32x2(a0), u1 = unpack_f32x2(a1);
    float2 u2 = unpack_f32x2(a2), u3 = unpack_f32x2(a3);
    float s01 = (u0.x + u0.y) + (u1.x + u1.y);
    float s23 = (u2.x + u2.y) + (u3.x + u3.y);
    float h2 = fast_tanh(s01 + s23);
    float biased = fmaf(h2, tw3q, 12582912.0f);   // tw3*h2*2^17 + magic
    int xi = __float_as_int(biased) - 0x4B400000;
    int s;
    asm("redux.sync.add.s32 %0, %1, 0xffffffff;" : "=r"(s) : "r"(xi));
    return __int_as_float(s + 0x4B400000) - 12582912.0f;   // (float)sum*2^17
}

// 4-point Lagrange cubic interpolation of g at tau.
__device__ __forceinline__ float g_interp(const float* __restrict__ sGw,
                                          float tau, float inv_h) {
    float s = fmaf(tau, inv_h, 1.0f);
    float fi = floorf(s);
    int i = (int)fi;
    i = i < 1 ? 1 : (i > NSEG ? NSEG : i);
    float u = s - (float)i;
    float p0 = sGw[i - 1], p1 = sGw[i], p2 = sGw[i + 1], p3 = sGw[i + 2];
    float um1 = u - 1.0f, um2 = u - 2.0f, up1 = u + 1.0f;
    float w0 = (-1.0f / 6.0f) * u * um1 * um2;
    float w1 = 0.5f * up1 * um1 * um2;
    float w2 = -0.5f * up1 * u * um2;
    float w3 = (1.0f / 6.0f) * up1 * u * um1;
    return fmaf(w0, p0, fmaf(w1, p1, fmaf(w2, p2, w3 * p3)));
}

// ---------------------------------------------------------------------------
// Single fused kernel.
// ---------------------------------------------------------------------------
__global__ void __launch_bounds__(BLOCK, 1)
neural_ode_kernel(const float* __restrict__ t,
                  const float* __restrict__ pW1, const float* __restrict__ pb1,
                  const float* __restrict__ pW2, const float* __restrict__ pb2,
                  const float* __restrict__ pW3, const float* __restrict__ pb3,
                  const float* __restrict__ dW, const float* __restrict__ db,
                  const float* __restrict__ tW1, const float* __restrict__ tb1,
                  const float* __restrict__ tW2, const float* __restrict__ tb2,
                  const float* __restrict__ tW3, const float* __restrict__ tb3,
                  float* __restrict__ out) {
    __shared__ float sW2T[64 * 65];   // pW2 transposed, padded (prologue only)
    __shared__ float sT2T[32 * 33];   // tW2 transposed staging
    __shared__ float sW1a[64], sW1b[64], sPb1[64], sPb2[64], sw[64];
    __shared__ float sFoldP[4][64];
    __shared__ float sCp[64];
    __shared__ float sT1a[32], sT1b[32], sTb1[32], sTb2[32], sTw3[32];
    __shared__ float sScal[3];        // c_fold, db0, tb3_0
    __shared__ float sG[WARPS_PER_BLOCK][NG];
    __shared__ __align__(16) float2 sPair[WARPS_PER_BLOCK][2][4][32];
    __shared__ __align__(16) float sHv[WARPS_PER_BLOCK][2][32];

    int tid = threadIdx.x;
    for (int idx = tid; idx < 4096; idx += BLOCK) {
        int j = idx >> 6, k = idx & 63;
        sW2T[k * 65 + j] = pW2[idx];
    }
    for (int idx = tid; idx < 1024; idx += BLOCK) {
        int j = idx >> 5, k = idx & 31;
        sT2T[k * 33 + j] = tW2[idx];
    }
    // Cooperative decoder fold: w_j = sum_i dW[i]*pW3[i][j]
    {
        int q = tid >> 6, j = tid & 63;
        float p = 0.0f;
        #pragma unroll
        for (int i = 0; i < 16; ++i)
            p = fmaf(dW[q * 16 + i], pW3[(q * 16 + i) * 64 + j], p);
        sFoldP[q][j] = p;
    }
    if (tid < 64) {
        sW1a[tid] = pW1[2 * tid];
        sW1b[tid] = pW1[2 * tid + 1];
        sPb1[tid] = pb1[tid];
        sPb2[tid] = pb2[tid];
        sCp[tid]  = dW[tid] * pb3[tid];
    }
    if (tid < 32) {
        sT1a[tid] = tW1[2 * tid];
        sT1b[tid] = tW1[2 * tid + 1];
        sTb1[tid] = tb1[tid];
        sTb2[tid] = tb2[tid];
        sTw3[tid] = tW3[tid];
    }
    __syncthreads();
    if (tid < 64)
        sw[tid] = (sFoldP[0][tid] + sFoldP[1][tid]) + (sFoldP[2][tid] + sFoldP[3][tid]);
    if (tid == 0) {
        float c = 0.0f;
        #pragma unroll
        for (int i = 0; i < 64; ++i) c += sCp[i];
        sScal[0] = c;
        sScal[1] = db[0];
        sScal[2] = tb3[0];
    }
    __syncthreads();

    int warp = tid >> 5, lane = tid & 31;
    int b = blockIdx.x * WARPS_PER_BLOCK + warp;

    // theta layer-2 weight column -> packed 64-bit register pairs
    unsigned long long w2p[16];
    #pragma unroll
    for (int kk = 0; kk < 16; ++kk)
        w2p[kk] = pack_f32x2(sT2T[(2 * kk) * 33 + lane],
                             sT2T[(2 * kk + 1) * 33 + lane]);

    float w1a_lo = sW1a[lane],       w1b_lo = sW1b[lane];
    float w1a_hi = sW1a[lane + 32],  w1b_hi = sW1b[lane + 32];
    float b1_lo  = sPb1[lane],       b1_hi  = sPb1[lane + 32];
    float b2_lo  = sPb2[lane],       b2_hi  = sPb2[lane + 32];
    float w_lo   = sw[lane],         w_hi   = sw[lane + 32];
    float cfold = sScal[0], db0 = sScal[1], tb30 = sScal[2];

    float t1 = t[b];
    float h = t1 * (1.0f / (float)NSEG);

    // ---- Per-warp g-grid tabulation: NBATCH batches of 4 points.
    for (int batch = 0; batch < NBATCH; ++batch) {
        int j4 = batch * 4;
        int pb = batch & 1;
        float taus[4];
        #pragma unroll
        for (int s = 0; s < 4; ++s) taus[s] = (float)(j4 + s - 1) * h;

        #pragma unroll
        for (int s = 0; s < 4; ++s) {
            float lo = fast_tanh(fmaf(w1a_lo, t1, fmaf(w1b_lo, taus[s], b1_lo)));
            float hi = fast_tanh(fmaf(w1a_hi, t1, fmaf(w1b_hi, taus[s], b1_hi)));
            sPair[warp][pb][s][lane] = make_float2(lo, hi);
        }
        __syncwarp();

        float acc_lo[4], acc_hi[4];
        #pragma unroll
        for (int s = 0; s < 4; ++s) { acc_lo[s] = b2_lo; acc_hi[s] = b2_hi; }

        #pragma unroll 4
        for (int k = 0; k < 32; ++k) {
            float2 p0 = sPair[warp][pb][0][k];
            float2 p1 = sPair[warp][pb][1][k];
            float2 p2 = sPair[warp][pb][2][k];
            float2 p3 = sPair[warp][pb][3][k];
            float wA = sW2T[k * 65 + lane];
            float wB = sW2T[(k + 32) * 65 + lane];
            float wC = sW2T[k * 65 + lane + 32];
            float wD = sW2T[(k + 32) * 65 + lane + 32];
            acc_lo[0] = fmaf(wA, p0.x, fmaf(wB, p0.y, acc_lo[0]));
            acc_hi[0] = fmaf(wC, p0.x, fmaf(wD, p0.y, acc_hi[0]));
            acc_lo[1] = fmaf(wA, p1.x, fmaf(wB, p1.y, acc_lo[1]));
            acc_hi[1] = fmaf(wC, p1.x, fmaf(wD, p1.y, acc_hi[1]));
            acc_lo[2] = fmaf(wA, p2.x, fmaf(wB, p2.y, acc_lo[2]));
            acc_hi[2] = fmaf(wC, p2.x, fmaf(wD, p2.y, acc_hi[2]));
            acc_lo[3] = fmaf(wA, p3.x, fmaf(wB, p3.y, acc_lo[3]));
            acc_hi[3] = fmaf(wC, p3.x, fmaf(wD, p3.y, acc_hi[3]));
        }
        #pragma unroll
        for (int s = 0; s < 4; ++s) {
            float v = fmaf(w_lo, fast_tanh(acc_lo[s]), w_hi * fast_tanh(acc_hi[s]));
            v = warp_sum(v) + cfold;
            if (lane == 0) sG[warp][j4 + s] = v;
        }
        __syncwarp();
    }
    const float* sGw = sG[warp];

    float ta  = sT1a[lane], tbw = sT1b[lane], tb1r = sTb1[lane];
    float tb2r = sTb2[lane];
    float tw3q = sTw3[lane] * 131072.0f;   // tw3 * 2^17 (quantizer fold)

    const float C2 = 0.2f, C3 = 0.3f, C4 = 0.8f, C5 = (float)(8.0 / 9.0);
    const float A21 = 0.2f;
    const float A31 = (float)(3.0 / 40.0),   A32 = (float)(9.0 / 40.0);
    const float A41 = (float)(44.0 / 45.0),  A42 = (float)(-56.0 / 15.0), A43 = (float)(32.0 / 9.0);
    const float A51 = (float)(19372.0 / 6561.0), A52 = (float)(-25360.0 / 2187.0);
    const float A53 = (float)(64448.0 / 6561.0), A54 = (float)(-212.0 / 729.0);
    const float A61 = (float)(9017.0 / 3168.0),  A62 = (float)(-355.0 / 33.0);
    const float A63 = (float)(46732.0 / 5247.0), A64 = (float)(49.0 / 176.0);
    const float A65 = (float)(-5103.0 / 18656.0);
    const float B1 = (float)(35.0 / 384.0), B3 = (float)(500.0 / 1113.0);
    const float B4 = (float)(125.0 / 192.0), B5 = (float)(-2187.0 / 6784.0);
    const float B6 = (float)(11.0 / 84.0);
    const float E1 = (float)(35.0 / 384.0 - 5179.0 / 57600.0);
    const float E3 = (float)(500.0 / 1113.0 - 7571.0 / 16695.0);
    const float E4 = (float)(125.0 / 192.0 - 393.0 / 640.0);
    const float E5 = (float)(-2187.0 / 6784.0 + 92097.0 / 339200.0);
    const float E6 = (float)(11.0 / 84.0 - 187.0 / 2100.0);
    const float E7 = (float)(-1.0 / 40.0);
    const float RTOL = 1e-3f, ATOL = 1e-6f;
    const float SAFETY = 0.9f, FMIN = 0.2f, FMAX = 10.0f;

    // per-lane stage coefficients: ta*c_s (serial-path shortening)
    float taC2 = ta * C2, taC3 = ta * C3, taC4 = ta * C4, taC5 = ta * C5;

    float inv_h = __fdividef((float)NSEG, t1);
    float tau = 0.0f, y = 0.0f, dt = 0.01f;

    int tb = 0;  // buffer parity for hv broadcasts

    // Carries: fs1 (raw theta count at (tau,y)), g0 = g(tau), preTau = ta*tau+tb1.
    float fs1 = theta_raw(tb1r, 0.0f, tbw, tb2r, tw3q, w2p, sHv[warp][tb], lane);
    float g0  = g_interp(sGw, 0.0f, inv_h);
    float preTau = tb1r;

    for (int it = 0; it < MAX_STEPS; ++it) {
        float remaining = t1 - tau;
        if (remaining <= 1e-10f) break;
        float dt_eff = fminf(dt, remaining);

        float taus1 = tau + C2 * dt_eff;
        float taus2 = tau + C3 * dt_eff;
        float taus3 = tau + C4 * dt_eff;
        float taus4 = tau + C5 * dt_eff;
        float taus5 = tau + dt_eff;

        // stage tanh inputs: one FMA after dt_eff (preTau carried)
        float pre1 = fmaf(taC2, dt_eff, preTau);
        float pre2 = fmaf(taC3, dt_eff, preTau);
        float pre3 = fmaf(taC4, dt_eff, preTau);
        float pre4 = fmaf(taC5, dt_eff, preTau);
        float pre5 = fmaf(ta,   dt_eff, preTau);

        // g at stage taus (g0 carried); per-stage affine folds off-chain.
        float g1 = g_interp(sGw, taus1, inv_h);
        float g2 = g_interp(sGw, taus2, inv_h);
        float g3 = g_interp(sGw, taus3, inv_h);
        float g4 = g_interp(sGw, taus4, inv_h);
        float g5 = g_interp(sGw, taus5, inv_h);
        float g0scl = g0 * INV17, g0aff = fmaf(g0, tb30, db0);
        float g1scl = g1 * INV17, g1aff = fmaf(g1, tb30, db0);
        float g2scl = g2 * INV17, g2aff = fmaf(g2, tb30, db0);
        float g3scl = g3 * INV17, g3aff = fmaf(g3, tb30, db0);
        float g4scl = g4 * INV17, g4aff = fmaf(g4, tb30, db0);
        float g5scl = g5 * INV17, g5aff = fmaf(g5, tb30, db0);

        float k1 = fmaf(fs1, g0scl, g0aff);

        float y2 = fmaf(dt_eff, A21 * k1, y);
        tb ^= 1;
        float fs2 = theta_raw(pre1, y2, tbw, tb2r, tw3q, w2p, sHv[warp][tb], lane);
        float k2 = fmaf(fs2, g1scl, g1aff);

        float y3 = fmaf(dt_eff, fmaf(A31, k1, A32 * k2), y);
        tb ^= 1;
        float fs3 = theta_raw(pre2, y3, tbw, tb2r, tw3q, w2p, sHv[warp][tb], lane);
        float k3 = fmaf(fs3, g2scl, g2aff);

        float y4 = fmaf(dt_eff, fmaf(A41, k1, fmaf(A42, k2, A43 * k3)), y);
        tb ^= 1;
        float fs4 = theta_raw(pre3, y4, tbw, tb2r, tw3q, w2p, sHv[warp][tb], lane);
        float k4 = fmaf(fs4, g3scl, g3aff);

        float y5i = fmaf(dt_eff, fmaf(A51, k1, fmaf(A52, k2, fmaf(A53, k3, A54 * k4))), y);
        tb ^= 1;
        float fs5 = theta_raw(pre4, y5i, tbw, tb2r, tw3q, w2p, sHv[warp][tb], lane);
        float k5 = fmaf(fs5, g4scl, g4aff);

        float y6 = fmaf(dt_eff, fmaf(A61, k1, fmaf(A62, k2, fmaf(A63, k3, fmaf(A64, k4, A65 * k5)))), y);
        tb ^= 1;
        float fs6 = theta_raw(pre5, y6, tbw, tb2r, tw3q, w2p, sHv[warp][tb], lane);
        float k6 = fmaf(fs6, g5scl, g5aff);

        float y5 = fmaf(dt_eff,
                        fmaf(B1, k1, fmaf(B3, k3, fmaf(B4, k4, fmaf(B5, k5, B6 * k6)))),
                        y);
        tb ^= 1;
        float fs7 = theta_raw(pre5, y5, tbw, tb2r, tw3q, w2p, sHv[warp][tb], lane);
        float k7 = fmaf(fs7, g5scl, g5aff);

        float err = dt_eff *
            fmaf(E1, k1, fmaf(E3, k3, fmaf(E4, k4, fmaf(E5, k5, fmaf(E6, k6, E7 * k7)))));
        float scale = fmaf(RTOL, fmaxf(fabsf(y), fabsf(y5)), ATOL);

        // Division-free controller.
        // accept: err_norm = sqrt(e2/s2 + 1e-30) <= 1  <=>  e2 <= s2 (boundary-
        // identical: the 1e-30 shifts the threshold by <1 ulp of 1.0).
        // factor  = SAFETY * max(r2+1e-30, 1e-20)^-0.1
        //         = SAFETY * exp2(-0.1 * max(lg2(e2)-lg2(s2), -66.439))
        //   (the +1e-30 only matters for r2 < 1e-28, where the -66.4 clamp
        //    makes factor hit the FMAX=10 clip either way).
        // Both lg2's are independent MUFUs -> issue in parallel; no divide.
        float e2 = err * err;
        float s2 = scale * scale;
        bool accept = (e2 <= s2);
        float le = __log2f(fmaxf(e2, 1e-38f));
        float ls = __log2f(s2);
        float d = fmaxf(le - ls, -66.439f);
        float factor = SAFETY * exp2f(-0.1f * d);
        factor = fminf(fmaxf(factor, FMIN), FMAX);

        if (accept) {
            tau = taus5;
            y = y5;
            fs1 = fs7;       // FSAL hand-off (raw count)
            g0 = g5;         // g(tau_new) == g5 bitwise
            preTau = pre5;   // ta*tau_new + tb1
        }
        dt = fmaxf(dt_eff * factor, 1e-8f);
    }

    if (lane == 0) out[b] = y;
}

extern "C" void kernel_launch(void* const* d_in, const int* in_sizes, int n_in,
                              void* d_out, int out_size) {
    const float* t    = (const float*)d_in[0];
    const float* pW1  = (const float*)d_in[1];
    const float* pb1  = (const float*)d_in[2];
    const float* pW2  = (const float*)d_in[3];
    const float* pb2  = (const float*)d_in[4];
    const float* pW3  = (const float*)d_in[5];
    const float* pb3  = (const float*)d_in[6];
    const float* dW   = (const float*)d_in[7];
    const float* db   = (const float*)d_in[8];
    const float* tW1  = (const float*)d_in[9];
    const float* tb1  = (const float*)d_in[10];
    const float* tW2  = (const float*)d_in[11];
    const float* tb2  = (const float*)d_in[12];
    const float* tW3  = (const float*)d_in[13];
    const float* tb3  = (const float*)d_in[14];
    float* out = (float*)d_out;

    neural_ode_kernel<<<BATCH / WARPS_PER_BLOCK, BLOCK>>>(
        t, pW1, pb1, pW2, pb2, pW3, pb3, dW, db,
        tW1, tb1, tW2, tb2, tW3, tb3, out);
}

// round 14
// speedup vs baseline: 1.1181x; 1.0330x over previous
#include <cuda_runtime.h>
#include <math.h>

#define BATCH 1024
#define WARPS_PER_BLOCK 8
#define BLOCK (WARPS_PER_BLOCK * 32)
#define MAX_STEPS 128

// Grid tabulation of g(t1, tau): NG points, tau_j = (j-1)*h, h = t1/NSEG
#define NG 8
#define NSEG 5
#define NBATCH 2

#define INV17 7.62939453125e-06f   // 2^-17

// Fast warp sum via integer redux (sm_80+). Fixed-point 2^-17 quantization.
__device__ __forceinline__ float warp_sum(float v) {
    float biased = fmaf(v, 131072.0f, 12582912.0f);   // v*2^17 + 1.5*2^23
    int xi = __float_as_int(biased) - 0x4B400000;     // round(v*2^17)
    int s;
    asm("redux.sync.add.s32 %0, %1, 0xffffffff;" : "=r"(s) : "r"(xi));
    float fs = __int_as_float(s + 0x4B400000) - 12582912.0f;  // (float)s
    return fs * INV17;
}

// Hardware MUFU tanh (sm_75+): ~16 cyc, max abs err ~5e-4
__device__ __forceinline__ float fast_tanh(float x) {
    float r;
    asm("tanh.approx.f32 %0, %1;" : "=f"(r) : "f"(x));
    return r;
}

// ---- Packed fp32x2 (Blackwell): exact fp32, half the issue slots ----
__device__ __forceinline__ unsigned long long pack_f32x2(float lo, float hi) {
    unsigned long long r;
    asm("mov.b64 %0, {%1, %2};" : "=l"(r) : "f"(lo), "f"(hi));
    return r;
}
__device__ __forceinline__ float2 unpack_f32x2(unsigned long long v) {
    float lo, hi;
    asm("mov.b64 {%0, %1}, %2;" : "=f"(lo), "=f"(hi) : "l"(v));
    return make_float2(lo, hi);
}
__device__ __forceinline__ unsigned long long fma_f32x2(
    unsigned long long a, unsigned long long b, unsigned long long c) {
    unsigned long long d;
    asm("fma.rn.f32x2 %0, %1, %2, %3;" : "=l"(d) : "l"(a), "l"(b), "l"(c));
    return d;
}
// packed add via the proven fma instruction: a*1 + b
#define ONE2 0x3F8000003F800000ULL
__device__ __forceinline__ unsigned long long add_f32x2(
    unsigned long long a, unsigned long long b) {
    return fma_f32x2(a, ONE2, b);
}

// theta MLP layer2+3 with PRECOMPUTED tanh argument (affine hand-off).
// Returns raw quantized count fs = sum_lanes(tw3*h2)*2^17.
// 8 packed accumulators: dot chain depth 2 FMAs + 3-level packed-add tree.
__device__ __forceinline__ float theta_raw_arg(float arg,
                                               float tb2r, float tw3q,
                                               const unsigned long long* __restrict__ w2p,
                                               float* __restrict__ hvbuf,
                                               int lane) {
    float hv = fast_tanh(arg);
    hvbuf[lane] = hv;
    asm volatile("" ::: "memory");
    const ulonglong2* h2p = (const ulonglong2*)hvbuf;
    unsigned long long z = pack_f32x2(0.0f, 0.0f);
    unsigned long long a0 = pack_f32x2(tb2r, 0.0f);
    unsigned long long a1 = z, a2 = z, a3 = z, a4 = z, a5 = z, a6 = z, a7 = z;
    ulonglong2 hA = h2p[0], hB = h2p[1], hC = h2p[2], hD = h2p[3];
    ulonglong2 hE = h2p[4], hF = h2p[5], hG = h2p[6], hH = h2p[7];
    a0 = fma_f32x2(w2p[0],  hA.x, a0);  a1 = fma_f32x2(w2p[1],  hA.y, a1);
    a2 = fma_f32x2(w2p[2],  hB.x, a2);  a3 = fma_f32x2(w2p[3],  hB.y, a3);
    a4 = fma_f32x2(w2p[4],  hC.x, a4);  a5 = fma_f32x2(w2p[5],  hC.y, a5);
    a6 = fma_f32x2(w2p[6],  hD.x, a6);  a7 = fma_f32x2(w2p[7],  hD.y, a7);
    a0 = fma_f32x2(w2p[8],  hE.x, a0);  a1 = fma_f32x2(w2p[9],  hE.y, a1);
    a2 = fma_f32x2(w2p[10], hF.x, a2);  a3 = fma_f32x2(w2p[11], hF.y, a3);
    a4 = fma_f32x2(w2p[12], hG.x, a4);  a5 = fma_f32x2(w2p[13], hG.y, a5);
    a6 = fma_f32x2(w2p[14], hH.x, a6);  a7 = fma_f32x2(w2p[15], hH.y, a7);
    unsigned long long s01 = add_f32x2(a0, a1), s23 = add_f32x2(a2, a3);
    unsigned long long s45 = add_f32x2(a4, a5), s67 = add_f32x2(a6, a7);
    unsigned long long sA = add_f32x2(add_f32x2(s01, s23), add_f32x2(s45, s67));
    float2 u = unpack_f32x2(sA);
    float h2 = fast_tanh(u.x + u.y);
    float biased = fmaf(h2, tw3q, 12582912.0f);
    int xi = __float_as_int(biased) - 0x4B400000;
    int s;
    asm("redux.sync.add.s32 %0, %1, 0xffffffff;" : "=r"(s) : "r"(xi));
    return __int_as_float(s + 0x4B400000) - 12582912.0f;
}

// 4-point Lagrange cubic interpolation of g at tau.
__device__ __forceinline__ float g_interp(const float* __restrict__ sGw,
                                          float tau, float inv_h) {
    float s = fmaf(tau, inv_h, 1.0f);
    float fi = floorf(s);
    int i = (int)fi;
    i = i < 1 ? 1 : (i > NSEG ? NSEG : i);
    float u = s - (float)i;
    float p0 = sGw[i - 1], p1 = sGw[i], p2 = sGw[i + 1], p3 = sGw[i + 2];
    float um1 = u - 1.0f, um2 = u - 2.0f, up1 = u + 1.0f;
    float w0 = (-1.0f / 6.0f) * u * um1 * um2;
    float w1 = 0.5f * up1 * um1 * um2;
    float w2 = -0.5f * up1 * u * um2;
    float w3 = (1.0f / 6.0f) * up1 * u * um1;
    return fmaf(w0, p0, fmaf(w1, p1, fmaf(w2, p2, w3 * p3)));
}

// ---------------------------------------------------------------------------
// Single fused kernel.
// ---------------------------------------------------------------------------
__global__ void __launch_bounds__(BLOCK, 1)
neural_ode_kernel(const float* __restrict__ t,
                  const float* __restrict__ pW1, const float* __restrict__ pb1,
                  const float* __restrict__ pW2, const float* __restrict__ pb2,
                  const float* __restrict__ pW3, const float* __restrict__ pb3,
                  const float* __restrict__ dW, const float* __restrict__ db,
                  const float* __restrict__ tW1, const float* __restrict__ tb1,
                  const float* __restrict__ tW2, const float* __restrict__ tb2,
                  const float* __restrict__ tW3, const float* __restrict__ tb3,
                  float* __restrict__ out) {
    __shared__ float sW2T[64 * 65];
    __shared__ float sT2T[32 * 33];
    __shared__ float sW1a[64], sW1b[64], sPb1[64], sPb2[64], sw[64];
    __shared__ float sFoldP[4][64];
    __shared__ float sCp[64];
    __shared__ float sT1a[32], sT1b[32], sTb1[32], sTb2[32], sTw3[32];
    __shared__ float sScal[3];
    __shared__ float sG[WARPS_PER_BLOCK][NG];
    __shared__ __align__(16) float2 sPair[WARPS_PER_BLOCK][2][4][32];
    __shared__ __align__(16) float sHv[WARPS_PER_BLOCK][2][32];

    int tid = threadIdx.x;
    for (int idx = tid; idx < 4096; idx += BLOCK) {
        int j = idx >> 6, k = idx & 63;
        sW2T[k * 65 + j] = pW2[idx];
    }
    for (int idx = tid; idx < 1024; idx += BLOCK) {
        int j = idx >> 5, k = idx & 31;
        sT2T[k * 33 + j] = tW2[idx];
    }
    {
        int q = tid >> 6, j = tid & 63;
        float p = 0.0f;
        #pragma unroll
        for (int i = 0; i < 16; ++i)
            p = fmaf(dW[q * 16 + i], pW3[(q * 16 + i) * 64 + j], p);
        sFoldP[q][j] = p;
    }
    if (tid < 64) {
        sW1a[tid] = pW1[2 * tid];
        sW1b[tid] = pW1[2 * tid + 1];
        sPb1[tid] = pb1[tid];
        sPb2[tid] = pb2[tid];
        sCp[tid]  = dW[tid] * pb3[tid];
    }
    if (tid < 32) {
        sT1a[tid] = tW1[2 * tid];
        sT1b[tid] = tW1[2 * tid + 1];
        sTb1[tid] = tb1[tid];
        sTb2[tid] = tb2[tid];
        sTw3[tid] = tW3[tid];
    }
    __syncthreads();
    if (tid < 64)
        sw[tid] = (sFoldP[0][tid] + sFoldP[1][tid]) + (sFoldP[2][tid] + sFoldP[3][tid]);
    if (tid == 0) {
        float c = 0.0f;
        #pragma unroll
        for (int i = 0; i < 64; ++i) c += sCp[i];
        sScal[0] = c;
        sScal[1] = db[0];
        sScal[2] = tb3[0];
    }
    __syncthreads();

    int warp = tid >> 5, lane = tid & 31;
    int b = blockIdx.x * WARPS_PER_BLOCK + warp;

    unsigned long long w2p[16];
    #pragma unroll
    for (int kk = 0; kk < 16; ++kk)
        w2p[kk] = pack_f32x2(sT2T[(2 * kk) * 33 + lane],
                             sT2T[(2 * kk + 1) * 33 + lane]);

    float w1a_lo = sW1a[lane],       w1b_lo = sW1b[lane];
    float w1a_hi = sW1a[lane + 32],  w1b_hi = sW1b[lane + 32];
    float b1_lo  = sPb1[lane],       b1_hi  = sPb1[lane + 32];
    float b2_lo  = sPb2[lane],       b2_hi  = sPb2[lane + 32];
    float w_lo   = sw[lane],         w_hi   = sw[lane + 32];
    float cfold = sScal[0], db0 = sScal[1], tb30 = sScal[2];

    float t1 = t[b];
    float h = t1 * (1.0f / (float)NSEG);

    // ---- Per-warp g-grid tabulation: NBATCH batches of 4 points.
    for (int batch = 0; batch < NBATCH; ++batch) {
        int j4 = batch * 4;
        int pb = batch & 1;
        float taus[4];
        #pragma unroll
        for (int s = 0; s < 4; ++s) taus[s] = (float)(j4 + s - 1) * h;

        #pragma unroll
        for (int s = 0; s < 4; ++s) {
            float lo = fast_tanh(fmaf(w1a_lo, t1, fmaf(w1b_lo, taus[s], b1_lo)));
            float hi = fast_tanh(fmaf(w1a_hi, t1, fmaf(w1b_hi, taus[s], b1_hi)));
            sPair[warp][pb][s][lane] = make_float2(lo, hi);
        }
        __syncwarp();

        float acc_lo[4], acc_hi[4];
        #pragma unroll
        for (int s = 0; s < 4; ++s) { acc_lo[s] = b2_lo; acc_hi[s] = b2_hi; }

        #pragma unroll 4
        for (int k = 0; k < 32; ++k) {
            float2 p0 = sPair[warp][pb][0][k];
            float2 p1 = sPair[warp][pb][1][k];
            float2 p2 = sPair[warp][pb][2][k];
            float2 p3 = sPair[warp][pb][3][k];
            float wA = sW2T[k * 65 + lane];
            float wB = sW2T[(k + 32) * 65 + lane];
            float wC = sW2T[k * 65 + lane + 32];
            float wD = sW2T[(k + 32) * 65 + lane + 32];
            acc_lo[0] = fmaf(wA, p0.x, fmaf(wB, p0.y, acc_lo[0]));
            acc_hi[0] = fmaf(wC, p0.x, fmaf(wD, p0.y, acc_hi[0]));
            acc_lo[1] = fmaf(wA, p1.x, fmaf(wB, p1.y, acc_lo[1]));
            acc_hi[1] = fmaf(wC, p1.x, fmaf(wD, p1.y, acc_hi[1]));
            acc_lo[2] = fmaf(wA, p2.x, fmaf(wB, p2.y, acc_lo[2]));
            acc_hi[2] = fmaf(wC, p2.x, fmaf(wD, p2.y, acc_hi[2]));
            acc_lo[3] = fmaf(wA, p3.x, fmaf(wB, p3.y, acc_lo[3]));
            acc_hi[3] = fmaf(wC, p3.x, fmaf(wD, p3.y, acc_hi[3]));
        }
        #pragma unroll
        for (int s = 0; s < 4; ++s) {
            float v = fmaf(w_lo, fast_tanh(acc_lo[s]), w_hi * fast_tanh(acc_hi[s]));
            v = warp_sum(v) + cfold;
            if (lane == 0) sG[warp][j4 + s] = v;
        }
        __syncwarp();
    }
    const float* sGw = sG[warp];

    float ta  = sT1a[lane], tbw = sT1b[lane], tb1r = sTb1[lane];
    float tb2r = sTb2[lane];
    float tw3q = sTw3[lane] * 131072.0f;

    const float C2 = 0.2f, C3 = 0.3f, C4 = 0.8f, C5 = (float)(8.0 / 9.0);
    const float A21 = 0.2f;
    const float A31 = (float)(3.0 / 40.0),   A32 = (float)(9.0 / 40.0);
    const float A41 = (float)(44.0 / 45.0),  A42 = (float)(-56.0 / 15.0), A43 = (float)(32.0 / 9.0);
    const float A51 = (float)(19372.0 / 6561.0), A52 = (float)(-25360.0 / 2187.0);
    const float A53 = (float)(64448.0 / 6561.0), A54 = (float)(-212.0 / 729.0);
    const float A61 = (float)(9017.0 / 3168.0),  A62 = (float)(-355.0 / 33.0);
    const float A63 = (float)(46732.0 / 5247.0), A64 = (float)(49.0 / 176.0);
    const float A65 = (float)(-5103.0 / 18656.0);
    const float B1 = (float)(35.0 / 384.0), B3 = (float)(500.0 / 1113.0);
    const float B4 = (float)(125.0 / 192.0), B5 = (float)(-2187.0 / 6784.0);
    const float B6 = (float)(11.0 / 84.0);
    const float E1 = (float)(35.0 / 384.0 - 5179.0 / 57600.0);
    const float E3 = (float)(500.0 / 1113.0 - 7571.0 / 16695.0);
    const float E4 = (float)(125.0 / 192.0 - 393.0 / 640.0);
    const float E5 = (float)(-2187.0 / 6784.0 + 92097.0 / 339200.0);
    const float E6 = (float)(11.0 / 84.0 - 187.0 / 2100.0);
    const float E7 = (float)(-1.0 / 40.0);
    const float RTOL = 1e-3f, ATOL = 1e-6f;
    const float FMIN = 0.2f, FMAX = 10.0f;
    const float LOG2_SAFETY = -0.15200309f;   // log2(0.9)

    float taC2 = ta * C2, taC3 = ta * C3, taC4 = ta * C4, taC5 = ta * C5;

    float inv_h = __fdividef((float)NSEG, t1);
    float tau = 0.0f, y = 0.0f, dt = 0.01f;
    float remaining = t1;

    int tb = 0;

    // Carries: fs1 (raw theta count at (tau,y)), g0scl/g0aff, preTau.
    float fs1 = theta_raw_arg(tb1r, tb2r, tw3q, w2p, sHv[warp][tb], lane);
    float g0i = g_interp(sGw, 0.0f, inv_h);
    float g0scl = g0i * INV17, g0aff = fmaf(g0i, tb30, db0);
    float preTau = tb1r;

    for (int it = 0; it < MAX_STEPS; ++it) {
        if (remaining <= 1e-10f) break;
        float dt_eff = fminf(dt, remaining);

        float taus1 = tau + C2 * dt_eff;
        float taus2 = tau + C3 * dt_eff;
        float taus3 = tau + C4 * dt_eff;
        float taus4 = tau + C5 * dt_eff;
        float taus5 = tau + dt_eff;

        float pre1 = fmaf(taC2, dt_eff, preTau);
        float pre2 = fmaf(taC3, dt_eff, preTau);
        float pre3 = fmaf(taC4, dt_eff, preTau);
        float pre4 = fmaf(taC5, dt_eff, preTau);
        float pre5 = fmaf(ta,   dt_eff, preTau);

        float g1 = g_interp(sGw, taus1, inv_h);
        float g2 = g_interp(sGw, taus2, inv_h);
        float g3 = g_interp(sGw, taus3, inv_h);
        float g4 = g_interp(sGw, taus4, inv_h);
        float g5 = g_interp(sGw, taus5, inv_h);
        float g1scl = g1 * INV17, g1aff = fmaf(g1, tb30, db0);
        float g2scl = g2 * INV17, g2aff = fmaf(g2, tb30, db0);
        float g3scl = g3 * INV17, g3aff = fmaf(g3, tb30, db0);
        float g4scl = g4 * INV17, g4aff = fmaf(g4, tb30, db0);
        float g5scl = g5 * INV17, g5aff = fmaf(g5, tb30, db0);

        // ---- stage 2
        float k1 = fmaf(fs1, g0scl, g0aff);
        float y2 = fmaf(dt_eff, A21 * k1, y);
        float arg2 = fmaf(tbw, y2, pre1);
        float fs2 = theta_raw_arg(arg2, tb2r, tw3q, w2p, sHv[warp][tb ^= 1], lane);

        // ---- stage 3 (arg affine in fs2; alpha/beta computed off-chain)
        float al3 = fmaf(dt_eff * A32, g1aff, fmaf(dt_eff * A31, k1, y));
        float be3 = (dt_eff * A32) * g1scl;
        float agA3 = fmaf(tbw, al3, pre2), agB3 = tbw * be3;
        float k2 = fmaf(fs2, g1scl, g1aff);
        float arg3 = fmaf(agB3, fs2, agA3);
        float fs3 = theta_raw_arg(arg3, tb2r, tw3q, w2p, sHv[warp][tb ^= 1], lane);

        // ---- stage 4
        float al4 = fmaf(dt_eff * A43, g2aff,
                     fmaf(dt_eff * A42, k2, fmaf(dt_eff * A41, k1, y)));
        float be4 = (dt_eff * A43) * g2scl;
        float agA4 = fmaf(tbw, al4, pre3), agB4 = tbw * be4;
        float k3 = fmaf(fs3, g2scl, g2aff);
        float arg4 = fmaf(agB4, fs3, agA4);
        float fs4 = theta_raw_arg(arg4, tb2r, tw3q, w2p, sHv[warp][tb ^= 1], lane);

        // ---- stage 5
        float al5 = fmaf(dt_eff * A54, g3aff,
                     fmaf(dt_eff * A53, k3,
                      fmaf(dt_eff * A52, k2, fmaf(dt_eff * A51, k1, y))));
        float be5 = (dt_eff * A54) * g3scl;
        float agA5 = fmaf(tbw, al5, pre4), agB5 = tbw * be5;
        float k4 = fmaf(fs4, g3scl, g3aff);
        float arg5 = fmaf(agB5, fs4, agA5);
        float fs5 = theta_raw_arg(arg5, tb2r, tw3q, w2p, sHv[warp][tb ^= 1], lane);

        // ---- stage 6
        float al6 = fmaf(dt_eff * A65, g4aff,
                     fmaf(dt_eff * A64, k4,
                      fmaf(dt_eff * A63, k3,
                       fmaf(dt_eff * A62, k2, fmaf(dt_eff * A61, k1, y)))));
        float be6 = (dt_eff * A65) * g4scl;
        float agA6 = fmaf(tbw, al6, pre5), agB6 = tbw * be6;
        float k5 = fmaf(fs5, g4scl, g4aff);
        float arg6 = fmaf(agB6, fs5, agA6);
        float fs6 = theta_raw_arg(arg6, tb2r, tw3q, w2p, sHv[warp][tb ^= 1], lane);

        // ---- stage 7 (y5 candidate affine in fs6)
        float alB = fmaf(dt_eff * B6, g5aff,
                     fmaf(dt_eff * B5, k5,
                      fmaf(dt_eff * B4, k4,
                       fmaf(dt_eff * B3, k3, fmaf(dt_eff * B1, k1, y)))));
        float beB = (dt_eff * B6) * g5scl;
        float agA7 = fmaf(tbw, alB, pre5), agB7 = tbw * beB;
        float k6 = fmaf(fs6, g5scl, g5aff);
        float y5 = fmaf(beB, fs6, alB);
        float arg7 = fmaf(agB7, fs6, agA7);
        float fs7 = theta_raw_arg(arg7, tb2r, tw3q, w2p, sHv[warp][tb ^= 1], lane);

        // ---- controller (err affine in fs7; s2/ls off-gate during stage 7)
        float scale = fmaf(RTOL, fmaxf(fabsf(y), fabsf(y5)), ATOL);
        float s2 = scale * scale;
        float ls = __log2f(s2);
        float alE = fmaf(dt_eff * E7, g5aff,
                     fmaf(dt_eff * E6, k6,
                      fmaf(dt_eff * E5, k5,
                       fmaf(dt_eff * E4, k4,
                        fmaf(dt_eff * E3, k3, (dt_eff * E1) * k1)))));
        float beE = (dt_eff * E7) * g5scl;
        float remNext = t1 - taus5;

        float err = fmaf(beE, fs7, alE);
        float e2 = err * err;
        bool accept = (e2 <= s2);
        float le = __log2f(fmaxf(e2, 1e-38f));
        float d = fmaxf(le - ls, -66.439f);
        float factor = exp2f(fmaf(-0.1f, d, LOG2_SAFETY));
        factor = fminf(fmaxf(factor, FMIN), FMAX);

        if (accept) {
            tau = taus5;
            y = y5;
            fs1 = fs7;
            g0scl = g5scl;
            g0aff = g5aff;
            preTau = pre5;
            remaining = remNext;
        }
        dt = fmaxf(dt_eff * factor, 1e-8f);
    }

    if (lane == 0) out[b] = y;
}

extern "C" void kernel_launch(void* const* d_in, const int* in_sizes, int n_in,
                              void* d_out, int out_size) {
    const float* t    = (const float*)d_in[0];
    const float* pW1  = (const float*)d_in[1];
    const float* pb1  = (const float*)d_in[2];
    const float* pW2  = (const float*)d_in[3];
    const float* pb2  = (const float*)d_in[4];
    const float* pW3  = (const float*)d_in[5];
    const float* pb3  = (const float*)d_in[6];
    const float* dW   = (const float*)d_in[7];
    const float* db   = (const float*)d_in[8];
    const float* tW1  = (const float*)d_in[9];
    const float* tb1  = (const float*)d_in[10];
    const float* tW2  = (const float*)d_in[11];
    const float* tb2  = (const float*)d_in[12];
    const float* tW3  = (const float*)d_in[13];
    const float* tb3  = (const float*)d_in[14];
    float* out = (float*)d_out;

    neural_ode_kernel<<<BATCH / WARPS_PER_BLOCK, BLOCK>>>(
        t, pW1, pb1, pW2, pb2, pW3, pb3, dW, db,
        tW1, tb1, tW2, tb2, tW3, tb3, out);
}

// round 16
// speedup vs baseline: 1.1459x; 1.0249x over previous
#include <cuda_runtime.h>
#include <math.h>

#define BATCH 1024
#define WARPS_PER_BLOCK 8
#define BLOCK (WARPS_PER_BLOCK * 32)
#define MAX_STEPS 128

// Grid tabulation of g(t1, tau): NG points, tau_j = (j-1)*h, h = t1/NSEG
#define NG 8
#define NSEG 5

#define INV17 7.62939453125e-06f   // 2^-17

// Fast warp sum via integer redux (sm_80+). Fixed-point 2^-17 quantization.
__device__ __forceinline__ float warp_sum(float v) {
    float biased = fmaf(v, 131072.0f, 12582912.0f);   // v*2^17 + 1.5*2^23
    int xi = __float_as_int(biased) - 0x4B400000;     // round(v*2^17)
    int s;
    asm("redux.sync.add.s32 %0, %1, 0xffffffff;" : "=r"(s) : "r"(xi));
    float fs = __int_as_float(s + 0x4B400000) - 12582912.0f;  // (float)s
    return fs * INV17;
}

// Hardware MUFU tanh (sm_75+): ~16 cyc, max abs err ~5e-4
__device__ __forceinline__ float fast_tanh(float x) {
    float r;
    asm("tanh.approx.f32 %0, %1;" : "=f"(r) : "f"(x));
    return r;
}

// ---- Packed fp32x2 (Blackwell): exact fp32, half the issue slots ----
__device__ __forceinline__ unsigned long long pack_f32x2(float lo, float hi) {
    unsigned long long r;
    asm("mov.b64 %0, {%1, %2};" : "=l"(r) : "f"(lo), "f"(hi));
    return r;
}
__device__ __forceinline__ float2 unpack_f32x2(unsigned long long v) {
    float lo, hi;
    asm("mov.b64 {%0, %1}, %2;" : "=f"(lo), "=f"(hi) : "l"(v));
    return make_float2(lo, hi);
}
__device__ __forceinline__ unsigned long long fma_f32x2(
    unsigned long long a, unsigned long long b, unsigned long long c) {
    unsigned long long d;
    asm("fma.rn.f32x2 %0, %1, %2, %3;" : "=l"(d) : "l"(a), "l"(b), "l"(c));
    return d;
}
#define ONE2 0x3F8000003F800000ULL
__device__ __forceinline__ unsigned long long add_f32x2(
    unsigned long long a, unsigned long long b) {
    return fma_f32x2(a, ONE2, b);
}

// theta MLP layer2+3 with PRECOMPUTED tanh argument (affine hand-off).
// Returns raw quantized count fs = sum_lanes(tw3*h2)*2^17.
__device__ __forceinline__ float theta_raw_arg(float arg,
                                               float tb2r, float tw3q,
                                               const unsigned long long* __restrict__ w2p,
                                               float* __restrict__ hvbuf,
                                               int lane) {
    float hv = fast_tanh(arg);
    hvbuf[lane] = hv;
    asm volatile("" ::: "memory");
    const ulonglong2* h2p = (const ulonglong2*)hvbuf;
    unsigned long long z = pack_f32x2(0.0f, 0.0f);
    unsigned long long a0 = pack_f32x2(tb2r, 0.0f);
    unsigned long long a1 = z, a2 = z, a3 = z, a4 = z, a5 = z, a6 = z, a7 = z;
    ulonglong2 hA = h2p[0], hB = h2p[1], hC = h2p[2], hD = h2p[3];
    ulonglong2 hE = h2p[4], hF = h2p[5], hG = h2p[6], hH = h2p[7];
    a0 = fma_f32x2(w2p[0],  hA.x, a0);  a1 = fma_f32x2(w2p[1],  hA.y, a1);
    a2 = fma_f32x2(w2p[2],  hB.x, a2);  a3 = fma_f32x2(w2p[3],  hB.y, a3);
    a4 = fma_f32x2(w2p[4],  hC.x, a4);  a5 = fma_f32x2(w2p[5],  hC.y, a5);
    a6 = fma_f32x2(w2p[6],  hD.x, a6);  a7 = fma_f32x2(w2p[7],  hD.y, a7);
    a0 = fma_f32x2(w2p[8],  hE.x, a0);  a1 = fma_f32x2(w2p[9],  hE.y, a1);
    a2 = fma_f32x2(w2p[10], hF.x, a2);  a3 = fma_f32x2(w2p[11], hF.y, a3);
    a4 = fma_f32x2(w2p[12], hG.x, a4);  a5 = fma_f32x2(w2p[13], hG.y, a5);
    a6 = fma_f32x2(w2p[14], hH.x, a6);  a7 = fma_f32x2(w2p[15], hH.y, a7);
    unsigned long long s01 = add_f32x2(a0, a1), s23 = add_f32x2(a2, a3);
    unsigned long long s45 = add_f32x2(a4, a5), s67 = add_f32x2(a6, a7);
    unsigned long long sA = add_f32x2(add_f32x2(s01, s23), add_f32x2(s45, s67));
    float2 u = unpack_f32x2(sA);
    float h2 = fast_tanh(u.x + u.y);
    float biased = fmaf(h2, tw3q, 12582912.0f);
    int xi = __float_as_int(biased) - 0x4B400000;
    int s;
    asm("redux.sync.add.s32 %0, %1, 0xffffffff;" : "=r"(s) : "r"(xi));
    return __int_as_float(s + 0x4B400000) - 12582912.0f;
}

// 4-point Lagrange cubic interpolation of g at tau.
__device__ __forceinline__ float g_interp(const float* __restrict__ sGw,
                                          float tau, float inv_h) {
    float s = fmaf(tau, inv_h, 1.0f);
    float fi = floorf(s);
    int i = (int)fi;
    i = i < 1 ? 1 : (i > NSEG ? NSEG : i);
    float u = s - (float)i;
    float p0 = sGw[i - 1], p1 = sGw[i], p2 = sGw[i + 1], p3 = sGw[i + 2];
    float um1 = u - 1.0f, um2 = u - 2.0f, up1 = u + 1.0f;
    float w0 = (-1.0f / 6.0f) * u * um1 * um2;
    float w1 = 0.5f * up1 * um1 * um2;
    float w2 = -0.5f * up1 * u * um2;
    float w3 = (1.0f / 6.0f) * up1 * u * um1;
    return fmaf(w0, p0, fmaf(w1, p1, fmaf(w2, p2, w3 * p3)));
}

// ---------------------------------------------------------------------------
// Single fused kernel.
// ---------------------------------------------------------------------------
__global__ void __launch_bounds__(BLOCK, 1)
neural_ode_kernel(const float* __restrict__ t,
                  const float* __restrict__ pW1, const float* __restrict__ pb1,
                  const float* __restrict__ pW2, const float* __restrict__ pb2,
                  const float* __restrict__ pW3, const float* __restrict__ pb3,
                  const float* __restrict__ dW, const float* __restrict__ db,
                  const float* __restrict__ tW1, const float* __restrict__ tb1,
                  const float* __restrict__ tW2, const float* __restrict__ tb2,
                  const float* __restrict__ tW3, const float* __restrict__ tb3,
                  float* __restrict__ out) {
    __shared__ float sW2T[64 * 65];
    __shared__ float sT2T[32 * 33];
    __shared__ float sW1a[64], sW1b[64], sPb1[64], sPb2[64], sw[64];
    __shared__ float sFoldP[4][64];
    __shared__ float sCp[64];
    __shared__ float sT1a[32], sT1b[32], sTb1[32], sTb2[32], sTw3[32];
    __shared__ float sScal[3];
    __shared__ float sG[WARPS_PER_BLOCK][NG];
    __shared__ __align__(16) float2 sPair[WARPS_PER_BLOCK][NG][32];
    __shared__ __align__(16) float sHv[WARPS_PER_BLOCK][2][32];

    int tid = threadIdx.x;
    for (int idx = tid; idx < 4096; idx += BLOCK) {
        int j = idx >> 6, k = idx & 63;
        sW2T[k * 65 + j] = pW2[idx];
    }
    for (int idx = tid; idx < 1024; idx += BLOCK) {
        int j = idx >> 5, k = idx & 31;
        sT2T[k * 33 + j] = tW2[idx];
    }
    {
        int q = tid >> 6, j = tid & 63;
        float p = 0.0f;
        #pragma unroll
        for (int i = 0; i < 16; ++i)
            p = fmaf(dW[q * 16 + i], pW3[(q * 16 + i) * 64 + j], p);
        sFoldP[q][j] = p;
    }
    if (tid < 64) {
        sW1a[tid] = pW1[2 * tid];
        sW1b[tid] = pW1[2 * tid + 1];
        sPb1[tid] = pb1[tid];
        sPb2[tid] = pb2[tid];
        sCp[tid]  = dW[tid] * pb3[tid];
    }
    if (tid < 32) {
        sT1a[tid] = tW1[2 * tid];
        sT1b[tid] = tW1[2 * tid + 1];
        sTb1[tid] = tb1[tid];
        sTb2[tid] = tb2[tid];
        sTw3[tid] = tW3[tid];
    }
    __syncthreads();
    if (tid < 64)
        sw[tid] = (sFoldP[0][tid] + sFoldP[1][tid]) + (sFoldP[2][tid] + sFoldP[3][tid]);
    if (tid == 0) {
        float c = 0.0f;
        #pragma unroll
        for (int i = 0; i < 64; ++i) c += sCp[i];
        sScal[0] = c;
        sScal[1] = db[0];
        sScal[2] = tb3[0];
    }
    __syncthreads();

    int warp = tid >> 5, lane = tid & 31;
    int b = blockIdx.x * WARPS_PER_BLOCK + warp;

    unsigned long long w2p[16];
    #pragma unroll
    for (int kk = 0; kk < 16; ++kk)
        w2p[kk] = pack_f32x2(sT2T[(2 * kk) * 33 + lane],
                             sT2T[(2 * kk + 1) * 33 + lane]);

    float w1a_lo = sW1a[lane],       w1b_lo = sW1b[lane];
    float w1a_hi = sW1a[lane + 32],  w1b_hi = sW1b[lane + 32];
    float b1_lo  = sPb1[lane],       b1_hi  = sPb1[lane + 32];
    float b2_lo  = sPb2[lane],       b2_hi  = sPb2[lane + 32];
    float w_lo   = sw[lane],         w_hi   = sw[lane + 32];
    float cfold = sScal[0], db0 = sScal[1], tb30 = sScal[2];

    float t1 = t[b];
    float h = t1 * (1.0f / (float)NSEG);

    // ---- Per-warp g-grid tabulation: ONE pass, all 8 points.
    {
        #pragma unroll
        for (int s = 0; s < NG; ++s) {
            float taus = (float)(s - 1) * h;
            float lo = fast_tanh(fmaf(w1a_lo, t1, fmaf(w1b_lo, taus, b1_lo)));
            float hi = fast_tanh(fmaf(w1a_hi, t1, fmaf(w1b_hi, taus, b1_hi)));
            sPair[warp][s][lane] = make_float2(lo, hi);
        }
        __syncwarp();

        float acc_lo[NG], acc_hi[NG];
        #pragma unroll
        for (int s = 0; s < NG; ++s) { acc_lo[s] = b2_lo; acc_hi[s] = b2_hi; }

        #pragma unroll 2
        for (int k = 0; k < 32; ++k) {
            float wA = sW2T[k * 65 + lane];
            float wB = sW2T[(k + 32) * 65 + lane];
            float wC = sW2T[k * 65 + lane + 32];
            float wD = sW2T[(k + 32) * 65 + lane + 32];
            #pragma unroll
            for (int s = 0; s < NG; ++s) {
                float2 p = sPair[warp][s][k];
                acc_lo[s] = fmaf(wA, p.x, fmaf(wB, p.y, acc_lo[s]));
                acc_hi[s] = fmaf(wC, p.x, fmaf(wD, p.y, acc_hi[s]));
            }
        }
        #pragma unroll
        for (int s = 0; s < NG; ++s) {
            float v = fmaf(w_lo, fast_tanh(acc_lo[s]), w_hi * fast_tanh(acc_hi[s]));
            v = warp_sum(v) + cfold;
            if (lane == 0) sG[warp][s] = v;
        }
        __syncwarp();
    }
    const float* sGw = sG[warp];

    float ta  = sT1a[lane], tbw = sT1b[lane], tb1r = sTb1[lane];
    float tb2r = sTb2[lane];
    float tw3q = sTw3[lane] * 131072.0f;

    const float C2 = 0.2f, C3 = 0.3f, C4 = 0.8f, C5 = (float)(8.0 / 9.0);
    const float A21 = 0.2f;
    const float A31 = (float)(3.0 / 40.0),   A32 = (float)(9.0 / 40.0);
    const float A41 = (float)(44.0 / 45.0),  A42 = (float)(-56.0 / 15.0), A43 = (float)(32.0 / 9.0);
    const float A51 = (float)(19372.0 / 6561.0), A52 = (float)(-25360.0 / 2187.0);
    const float A53 = (float)(64448.0 / 6561.0), A54 = (float)(-212.0 / 729.0);
    const float A61 = (float)(9017.0 / 3168.0),  A62 = (float)(-355.0 / 33.0);
    const float A63 = (float)(46732.0 / 5247.0), A64 = (float)(49.0 / 176.0);
    const float A65 = (float)(-5103.0 / 18656.0);
    const float B1 = (float)(35.0 / 384.0), B3 = (float)(500.0 / 1113.0);
    const float B4 = (float)(125.0 / 192.0), B5 = (float)(-2187.0 / 6784.0);
    const float B6 = (float)(11.0 / 84.0);
    const float E1 = (float)(35.0 / 384.0 - 5179.0 / 57600.0);
    const float E3 = (float)(500.0 / 1113.0 - 7571.0 / 16695.0);
    const float E4 = (float)(125.0 / 192.0 - 393.0 / 640.0);
    const float E5 = (float)(-2187.0 / 6784.0 + 92097.0 / 339200.0);
    const float E6 = (float)(11.0 / 84.0 - 187.0 / 2100.0);
    const float E7 = (float)(-1.0 / 40.0);
    const float RTOL = 1e-3f, ATOL = 1e-6f;
    const float FMIN = 0.2f, FMAX = 10.0f;
    const float LOG2_SAFETY = -0.15200309f;   // log2(0.9)

    float taC2 = ta * C2, taC3 = ta * C3, taC4 = ta * C4, taC5 = ta * C5;

    float inv_h = __fdividef((float)NSEG, t1);
    float tau = 0.0f, y = 0.0f, dt = 0.01f;
    float remaining = t1;

    int tb = 0;

    float fs1 = theta_raw_arg(tb1r, tb2r, tw3q, w2p, sHv[warp][tb], lane);
    float g0i = g_interp(sGw, 0.0f, inv_h);
    float g0scl = g0i * INV17, g0aff = fmaf(g0i, tb30, db0);
    float preTau = tb1r;
    float k1A21 = A21 * fmaf(fs1, g0scl, g0aff);   // A21*k1, gate-side precompute

    for (int it = 0; it < MAX_STEPS; ++it) {
        if (remaining <= 1e-10f) break;
        float dt_eff = fminf(dt, remaining);

        // ---- stage 2 first: shortest path from dt_eff (k1A21 precomputed)
        float pre1 = fmaf(taC2, dt_eff, preTau);
        float y2 = fmaf(dt_eff, k1A21, y);
        float arg2 = fmaf(tbw, y2, pre1);
        float fs2 = theta_raw_arg(arg2, tb2r, tw3q, w2p, sHv[warp][tb ^= 1], lane);

        float k1 = fmaf(fs1, g0scl, g0aff);   // exact k1, off-chain

        float taus1 = tau + C2 * dt_eff;
        float taus2 = tau + C3 * dt_eff;
        float taus3 = tau + C4 * dt_eff;
        float taus4 = tau + C5 * dt_eff;
        float taus5 = tau + dt_eff;

        float pre2 = fmaf(taC3, dt_eff, preTau);
        float pre3 = fmaf(taC4, dt_eff, preTau);
        float pre4 = fmaf(taC5, dt_eff, preTau);
        float pre5 = fmaf(ta,   dt_eff, preTau);

        float g1 = g_interp(sGw, taus1, inv_h);
        float g2 = g_interp(sGw, taus2, inv_h);
        float g3 = g_interp(sGw, taus3, inv_h);
        float g4 = g_interp(sGw, taus4, inv_h);
        float g5 = g_interp(sGw, taus5, inv_h);
        float g1scl = g1 * INV17, g1aff = fmaf(g1, tb30, db0);
        float g2scl = g2 * INV17, g2aff = fmaf(g2, tb30, db0);
        float g3scl = g3 * INV17, g3aff = fmaf(g3, tb30, db0);
        float g4scl = g4 * INV17, g4aff = fmaf(g4, tb30, db0);
        float g5scl = g5 * INV17, g5aff = fmaf(g5, tb30, db0);

        // ---- stage 3 (arg affine in fs2)
        float al3 = fmaf(dt_eff * A32, g1aff, fmaf(dt_eff * A31, k1, y));
        float be3 = (dt_eff * A32) * g1scl;
        float agA3 = fmaf(tbw, al3, pre2), agB3 = tbw * be3;
        float k2 = fmaf(fs2, g1scl, g1aff);
        float arg3 = fmaf(agB3, fs2, agA3);
        float fs3 = theta_raw_arg(arg3, tb2r, tw3q, w2p, sHv[warp][tb ^= 1], lane);

        // ---- stage 4
        float al4 = fmaf(dt_eff * A43, g2aff,
                     fmaf(dt_eff * A42, k2, fmaf(dt_eff * A41, k1, y)));
        float be4 = (dt_eff * A43) * g2scl;
        float agA4 = fmaf(tbw, al4, pre3), agB4 = tbw * be4;
        float k3 = fmaf(fs3, g2scl, g2aff);
        float arg4 = fmaf(agB4, fs3, agA4);
        float fs4 = theta_raw_arg(arg4, tb2r, tw3q, w2p, sHv[warp][tb ^= 1], lane);

        // ---- stage 5
        float al5 = fmaf(dt_eff * A54, g3aff,
                     fmaf(dt_eff * A53, k3,
                      fmaf(dt_eff * A52, k2, fmaf(dt_eff * A51, k1, y))));
        float be5 = (dt_eff * A54) * g3scl;
        float agA5 = fmaf(tbw, al5, pre4), agB5 = tbw * be5;
        float k4 = fmaf(fs4, g3scl, g3aff);
        float arg5 = fmaf(agB5, fs4, agA5);
        float fs5 = theta_raw_arg(arg5, tb2r, tw3q, w2p, sHv[warp][tb ^= 1], lane);

        // ---- stage 6
        float al6 = fmaf(dt_eff * A65, g4aff,
                     fmaf(dt_eff * A64, k4,
                      fmaf(dt_eff * A63, k3,
                       fmaf(dt_eff * A62, k2, fmaf(dt_eff * A61, k1, y)))));
        float be6 = (dt_eff * A65) * g4scl;
        float agA6 = fmaf(tbw, al6, pre5), agB6 = tbw * be6;
        float k5 = fmaf(fs5, g4scl, g4aff);
        float arg6 = fmaf(agB6, fs5, agA6);
        float fs6 = theta_raw_arg(arg6, tb2r, tw3q, w2p, sHv[warp][tb ^= 1], lane);

        // ---- stage 7 (y5 candidate affine in fs6)
        float alB = fmaf(dt_eff * B6, g5aff,
                     fmaf(dt_eff * B5, k5,
                      fmaf(dt_eff * B4, k4,
                       fmaf(dt_eff * B3, k3, fmaf(dt_eff * B1, k1, y)))));
        float beB = (dt_eff * B6) * g5scl;
        float agA7 = fmaf(tbw, alB, pre5), agB7 = tbw * beB;
        float k6 = fmaf(fs6, g5scl, g5aff);
        float y5 = fmaf(beB, fs6, alB);
        float arg7 = fmaf(agB7, fs6, agA7);
        float fs7 = theta_raw_arg(arg7, tb2r, tw3q, w2p, sHv[warp][tb ^= 1], lane);

        // ---- controller (err affine in fs7; everything else off-gate)
        float scale = fmaf(RTOL, fmaxf(fabsf(y), fabsf(y5)), ATOL);
        float s2 = scale * scale;
        float ls = __log2f(s2);
        float alE = fmaf(dt_eff * E7, g5aff,
                     fmaf(dt_eff * E6, k6,
                      fmaf(dt_eff * E5, k5,
                       fmaf(dt_eff * E4, k4,
                        fmaf(dt_eff * E3, k3, (dt_eff * E1) * k1)))));
        float beE = (dt_eff * E7) * g5scl;
        float remNext = t1 - taus5;
        // next-step k1A21 candidate (off-gate)
        float k7 = fmaf(fs7, g5scl, g5aff);
        float k1A21next = A21 * k7;

        float err = fmaf(beE, fs7, alE);
        float e2 = err * err;
        bool accept = (e2 <= s2);
        float le = __log2f(fmaxf(e2, 1e-38f));
        float d = fmaxf(le - ls, -66.439f);
        float factor = exp2f(fmaf(-0.1f, d, LOG2_SAFETY));
        factor = fminf(fmaxf(factor, FMIN), FMAX);

        if (accept) {
            tau = taus5;
            y = y5;
            fs1 = fs7;
            g0scl = g5scl;
            g0aff = g5aff;
            preTau = pre5;
            remaining = remNext;
            k1A21 = k1A21next;
        }
        dt = fmaxf(dt_eff * factor, 1e-8f);
    }

    if (lane == 0) out[b] = y;
}

extern "C" void kernel_launch(void* const* d_in, const int* in_sizes, int n_in,
                              void* d_out, int out_size) {
    const float* t    = (const float*)d_in[0];
    const float* pW1  = (const float*)d_in[1];
    const float* pb1  = (const float*)d_in[2];
    const float* pW2  = (const float*)d_in[3];
    const float* pb2  = (const float*)d_in[4];
    const float* pW3  = (const float*)d_in[5];
    const float* pb3  = (const float*)d_in[6];
    const float* dW   = (const float*)d_in[7];
    const float* db   = (const float*)d_in[8];
    const float* tW1  = (const float*)d_in[9];
    const float* tb1  = (const float*)d_in[10];
    const float* tW2  = (const float*)d_in[11];
    const float* tb2  = (const float*)d_in[12];
    const float* tW3  = (const float*)d_in[13];
    const float* tb3  = (const float*)d_in[14];
    float* out = (float*)d_out;

    neural_ode_kernel<<<BATCH / WARPS_PER_BLOCK, BLOCK>>>(
        t, pW1, pb1, pW2, pb2, pW3, pb3, dW, db,
        tW1, tb1, tW2, tb2, tW3, tb3, out);
}